// round 3
// baseline (speedup 1.0000x reference)
#include <cuda_runtime.h>
#include <cuda_bf16.h>
#include <math.h>

#define BATCH   16
#define CIN     256
#define HH      56
#define WW      56
#define HEADS   4
#define CPER    64
#define HB_N    (HEADS*BATCH)   // 64
#define NPIX    (HH*WW)         // 3136
#define NOUT    (BATCH*HEADS*CPER*NPIX)
#define BN_EPS  1e-5f

__device__ float g_xavg[BATCH*CIN];
__device__ int   g_act_idx[HB_N*256];
__device__ float g_act_val[HB_N*256];
__device__ int   g_act_cnt[HB_N];
__device__ float g_lasso_part[HB_N];

// =====================================================================
// Kernel 1: BN+ReLU fused global average pool
// =====================================================================
__global__ void bn_pool_kernel(const float* __restrict__ x,
                               const float* __restrict__ gmm,
                               const float* __restrict__ bet,
                               const float* __restrict__ mea,
                               const float* __restrict__ var)
{
    int bc = blockIdx.x;
    int c  = bc & (CIN-1);
    float a  = gmm[c] * rsqrtf(var[c] + BN_EPS);
    float sh = bet[c] - mea[c] * a;
    const float* xp = x + (size_t)bc * NPIX;
    float s = 0.f;
    for (int i = threadIdx.x; i < NPIX; i += 256)
        s += fmaxf(fmaf(xp[i], a, sh), 0.f);
    __shared__ float red[256];
    red[threadIdx.x] = s;
    __syncthreads();
    for (int st = 128; st > 0; st >>= 1) {
        if (threadIdx.x < st) red[threadIdx.x] += red[threadIdx.x + st];
        __syncthreads();
    }
    if (threadIdx.x == 0) g_xavg[bc] = red[0] * (1.f / (float)NPIX);
}

// =====================================================================
// Kernel 2: SE gate + exact top-k threshold + compaction
// =====================================================================
__global__ void se_kernel(const float* __restrict__ fc1,
                          const float* __restrict__ fc2,
                          const float* __restrict__ fcb,
                          const int*   inact_p)
{
    __shared__ float sav[256];
    __shared__ float sy[16];
    __shared__ float ssort[256];
    __shared__ int   wcnt[8];
    __shared__ int   woff[9];

    int hb = blockIdx.x;
    int h  = hb >> 4, b = hb & 15;
    int tid = threadIdx.x;

    sav[tid] = g_xavg[b*CIN + tid];
    __syncthreads();

    if (tid < 16) {
        const float* w = fc1 + (h*16 + tid)*256;
        float s = 0.f;
        #pragma unroll 8
        for (int c = 0; c < 256; ++c) s = fmaf(w[c], sav[c], s);
        sy[tid] = fmaxf(s, 0.f);
    }
    __syncthreads();

    float m;
    {
        const float* w = fc2 + ((size_t)(h*256 + tid)) * 16;
        float s = fcb[h*256 + tid];
        #pragma unroll
        for (int r = 0; r < 16; ++r) s = fmaf(w[r], sy[r], s);
        m = fmaxf(s, 0.f);
    }
    ssort[tid] = m;
    __syncthreads();

    sav[tid] = m;
    __syncthreads();
    for (int st = 128; st > 0; st >>= 1) {
        if (tid < st) sav[tid] += sav[tid + st];
        __syncthreads();
    }
    if (tid == 0) g_lasso_part[hb] = sav[0];
    __syncthreads();

    for (int k = 2; k <= 256; k <<= 1) {
        for (int j = k >> 1; j > 0; j >>= 1) {
            int ixj = tid ^ j;
            if (ixj > tid) {
                float va = ssort[tid], vb = ssort[ixj];
                bool up = ((tid & k) == 0);
                if ((va > vb) == up) { ssort[tid] = vb; ssort[ixj] = va; }
            }
            __syncthreads();
        }
    }

    int inact = 192;
    if (inact_p) {
        int iv = *inact_p;
        if (iv < 0 || iv > 256) {
            float f = __int_as_float(iv);
            iv = (f >= 0.f && f <= 256.f) ? (int)(f + 0.5f) : 192;
        }
        inact = iv;
    }
    float thresh = (inact > 0) ? ssort[min(inact,256) - 1] : -1e30f;

    bool keep = (m > thresh);
    unsigned ball = __ballot_sync(0xffffffffu, keep);
    int wid = tid >> 5, lane = tid & 31;
    if (lane == 0) wcnt[wid] = __popc(ball);
    __syncthreads();
    if (tid == 0) {
        int o = 0;
        #pragma unroll
        for (int w = 0; w < 8; ++w) { woff[w] = o; o += wcnt[w]; }
        woff[8] = o;
        g_act_cnt[hb] = o;
    }
    __syncthreads();
    int total = woff[8];
    int padded = (total + 15) & ~15;
    if (tid >= total && tid < padded) {
        g_act_idx[hb*256 + tid] = 0;
        g_act_val[hb*256 + tid] = 0.f;
    }
    if (keep) {
        int slot = woff[wid] + __popc(ball & ((1u << lane) - 1));
        g_act_idx[hb*256 + slot] = tid;
        g_act_val[hb*256 + slot] = m;
    }
}

__global__ void lasso_kernel(float* __restrict__ out)
{
    __shared__ float red[64];
    int tid = threadIdx.x;
    red[tid] = g_lasso_part[tid];
    __syncthreads();
    for (int st = 32; st > 0; st >>= 1) {
        if (tid < st) red[tid] += red[tid + st];
        __syncthreads();
    }
    if (tid == 0) out[NOUT] = red[0] * (1.f / (float)(BATCH*CIN));
}

// =====================================================================
// Kernel 3: sparse grouped conv, pre-duplicated-x f32x2 version.
//   x staged as (v,v) pairs; layout off(c) = c*2 + (c>>3)*4 floats,
//   row pitch 150 floats, per-ic block 900 floats.
//   weights [ic16][tap9][pitch 66 oc] -> broadcast LDS.64 pairs.
// grid = (14 row-tiles, 64 hb), block = 256 (8 warps; og=warp, pg=lane<28)
// =====================================================================
#define XDROW   150                 // floats per (ic,row)
#define XDIC    (6*XDROW)           // 900 floats per ic
#define XDSZ    (16*XDIC)           // 14400 floats
#define WPITCH  66
#define WSZ     (144*WPITCH)        // 9504 floats
#define SMEMF   (XDSZ + WSZ + 64*4)

typedef unsigned long long ull;

__device__ __forceinline__ ull fma2(ull a, ull b, ull c) {
    ull d;
    asm("fma.rn.f32x2 %0, %1, %2, %3;" : "=l"(d) : "l"(a), "l"(b), "l"(c));
    return d;
}

__global__ __launch_bounds__(256, 2)
void conv_kernel(const float* __restrict__ x,
                 const float* __restrict__ gmm,
                 const float* __restrict__ bet,
                 const float* __restrict__ mea,
                 const float* __restrict__ var,
                 const float* __restrict__ conv_w,   // [4][64][256][3][3]
                 float* __restrict__ out)
{
    extern __shared__ float smem[];
    float* sxd = smem;                  // duplicated x
    float* sw  = smem + XDSZ;           // weights
    float* sca = sw + WSZ;              // [64]
    float* scb = sca + 64;
    float* scm = scb + 64;
    int*   sch = (int*)(scm + 64);

    int hb = blockIdx.y;
    int h  = hb >> 4, b = hb & 15;
    int r0 = blockIdx.x * 4;

    int tid  = threadIdx.x;
    int og   = tid >> 5;               // warp id = oc group
    int pg   = tid & 31;               // lane; <28 active in compute
    int prow = pg / 7;                 // 0..3 (garbage for pg>=28, guarded)
    int pcol = (pg % 7) * 8;           // 0..48

    int cnt = g_act_cnt[hb];
    int nchunks = (cnt + 15) >> 4;

    // hoist all channel constants (up to 64, zero-padded by se_kernel)
    if (tid < 64) {
        int ch = 0; float mv = 0.f;
        if (tid < cnt) { ch = g_act_idx[hb*256 + tid]; mv = g_act_val[hb*256 + tid]; }
        float a  = gmm[ch] * rsqrtf(var[ch] + BN_EPS);
        sca[tid] = a;
        scb[tid] = bet[ch] - mea[ch] * a;
        scm[tid] = mv;
        sch[tid] = ch;
    }

    ull acc2[4][8];
    #pragma unroll
    for (int a = 0; a < 4; ++a)
        #pragma unroll
        for (int i = 0; i < 8; ++i) acc2[a][i] = 0ull;

    // thread's static x-window offsets (floats): XO(pcol) base
    int xo_base = pcol*2 + ((pcol >> 3) << 2);

    // staging assignments
    int xc  = tid & 63;                // column 0..63 (<60 active)
    int xs0 = tid >> 6;                // strip start 0..3
    // weight staging start: idx = tid, oc = tid/144? use rem/oc incremental
    // (recomputed each chunk below)

    __syncthreads();   // consts visible

    for (int ck = 0; ck < nchunks; ++ck) {
        if (ck) __syncthreads();   // protect smem from previous compute

        // ---- stage duplicated x: strips s = icc*6+rr, thread handles col xc
        if (xc < 60) {
            int icc = 0, rr = xs0;
            int gc = xc - 1;
            #pragma unroll 4
            for (int s = xs0; s < 96; s += 4) {
                int chn = ck*16 + icc;
                float mv = scm[chn];
                int gr = r0 - 1 + rr;
                float v = 0.f;
                if ((unsigned)gr < (unsigned)HH && (unsigned)gc < (unsigned)WW && mv != 0.f) {
                    float xv = x[(((size_t)b*CIN + sch[chn])*HH + gr)*WW + gc];
                    v = fmaxf(fmaf(xv, sca[chn], scb[chn]), 0.f) * mv;
                }
                float* dst = sxd + icc*XDIC + rr*XDROW + xc*2 + ((xc >> 3) << 2);
                *reinterpret_cast<float2*>(dst) = make_float2(v, v);
                rr += 4; if (rr >= 6) { rr -= 6; ++icc; }
            }
        }

        // ---- stage weights: [icc][tap][oc] pitch 66
        {
            int oc  = tid / 144;        // 0 or 1 at start
            int rem = tid - oc*144;
            #pragma unroll 4
            for (int k = 0; k < 36; ++k) {
                int icc = rem / 9;      // 0..15
                int tap = rem - icc*9;
                int chn = sch[ck*16 + icc];
                sw[(icc*9 + tap)*WPITCH + oc] =
                    conv_w[(((size_t)(h*CPER + oc))*CIN + chn)*9 + tap];
                rem += 256;
                while (rem >= 144) { rem -= 144; ++oc; }
            }
        }
        __syncthreads();

        // ---- compute
        if (pg < 28) {
            #pragma unroll 1
            for (int icc = 0; icc < 16; ++icc) {
                const float* xb = sxd + icc*XDIC + prow*XDROW + xo_base;
                const float* wb = sw + icc*9*WPITCH + og*8;
                #pragma unroll
                for (int ky = 0; ky < 3; ++ky) {
                    const ull* xr = reinterpret_cast<const ull*>(xb + ky*XDROW);
                    ull xd[10];
                    #pragma unroll
                    for (int i = 0; i < 8; ++i) xd[i] = xr[i];
                    xd[8] = xr[10];
                    xd[9] = xr[11];
                    #pragma unroll
                    for (int kx = 0; kx < 3; ++kx) {
                        const float* wp = wb + (ky*3 + kx)*WPITCH;
                        ull w0 = *reinterpret_cast<const ull*>(wp + 0);
                        ull w1 = *reinterpret_cast<const ull*>(wp + 2);
                        ull w2 = *reinterpret_cast<const ull*>(wp + 4);
                        ull w3 = *reinterpret_cast<const ull*>(wp + 6);
                        #pragma unroll
                        for (int i = 0; i < 8; ++i) {
                            ull xv = xd[kx + i];
                            acc2[0][i] = fma2(w0, xv, acc2[0][i]);
                            acc2[1][i] = fma2(w1, xv, acc2[1][i]);
                            acc2[2][i] = fma2(w2, xv, acc2[2][i]);
                            acc2[3][i] = fma2(w3, xv, acc2[3][i]);
                        }
                    }
                }
            }
        }
    }

    if (pg < 28) {
        #pragma unroll
        for (int a = 0; a < 4; ++a) {
            float lo[8], hi[8];
            #pragma unroll
            for (int i = 0; i < 8; ++i) {
                unsigned l32, h32;
                asm("mov.b64 {%0, %1}, %2;" : "=r"(l32), "=r"(h32) : "l"(acc2[a][i]));
                lo[i] = __uint_as_float(l32);
                hi[i] = __uint_as_float(h32);
            }
            int oc0 = og*8 + 2*a;
            size_t base0 = (((size_t)b*(HEADS*CPER) + (oc0*HEADS + h))*HH + (r0 + prow))*WW + pcol;
            size_t base1 = (((size_t)b*(HEADS*CPER) + ((oc0+1)*HEADS + h))*HH + (r0 + prow))*WW + pcol;
            *reinterpret_cast<float4*>(out + base0)     = make_float4(lo[0], lo[1], lo[2], lo[3]);
            *reinterpret_cast<float4*>(out + base0 + 4) = make_float4(lo[4], lo[5], lo[6], lo[7]);
            *reinterpret_cast<float4*>(out + base1)     = make_float4(hi[0], hi[1], hi[2], hi[3]);
            *reinterpret_cast<float4*>(out + base1 + 4) = make_float4(hi[4], hi[5], hi[6], hi[7]);
        }
    }
}

// =====================================================================
extern "C" void kernel_launch(void* const* d_in, const int* in_sizes, int n_in,
                              void* d_out, int out_size)
{
    const float* x    = (const float*)d_in[0];
    const float* gmm  = (const float*)d_in[1];
    const float* bet  = (const float*)d_in[2];
    const float* mea  = (const float*)d_in[3];
    const float* var  = (const float*)d_in[4];
    const float* fc1  = (const float*)d_in[5];
    const float* fc2  = (const float*)d_in[6];
    const float* fcb  = (const float*)d_in[7];
    const float* cw   = (const float*)d_in[8];
    const int*   inact = (n_in > 9) ? (const int*)d_in[9] : nullptr;
    float* out = (float*)d_out;

    bn_pool_kernel<<<BATCH*CIN, 256>>>(x, gmm, bet, mea, var);
    se_kernel<<<HB_N, 256>>>(fc1, fc2, fcb, inact);
    if (out_size > NOUT) lasso_kernel<<<1, 64>>>(out);

    size_t smem_bytes = SMEMF * sizeof(float);
    cudaFuncSetAttribute(conv_kernel, cudaFuncAttributeMaxDynamicSharedMemorySize,
                         (int)smem_bytes);
    dim3 grid(HH/4, HB_N);
    conv_kernel<<<grid, 256, smem_bytes>>>(x, gmm, bet, mea, var, cw, out);
}

// round 4
// speedup vs baseline: 1.0004x; 1.0004x over previous
#include <cuda_runtime.h>
#include <cuda_bf16.h>
#include <math.h>

#define BATCH   16
#define CIN     256
#define HH      56
#define WW      56
#define HEADS   4
#define CPER    64
#define HB_N    (HEADS*BATCH)   // 64
#define NPIX    (HH*WW)         // 3136
#define NOUT    (BATCH*HEADS*CPER*NPIX)
#define BN_EPS  1e-5f

__device__ float g_xavg[BATCH*CIN];
__device__ int   g_act_idx[HB_N*256];
__device__ float g_act_val[HB_N*256];
__device__ int   g_act_cnt[HB_N];
__device__ float g_lasso_part[HB_N];

// =====================================================================
// Kernel 1: BN+ReLU fused global average pool
// =====================================================================
__global__ void bn_pool_kernel(const float* __restrict__ x,
                               const float* __restrict__ gmm,
                               const float* __restrict__ bet,
                               const float* __restrict__ mea,
                               const float* __restrict__ var)
{
    int bc = blockIdx.x;
    int c  = bc & (CIN-1);
    float a  = gmm[c] * rsqrtf(var[c] + BN_EPS);
    float sh = bet[c] - mea[c] * a;
    const float* xp = x + (size_t)bc * NPIX;
    float s = 0.f;
    for (int i = threadIdx.x; i < NPIX; i += 256)
        s += fmaxf(fmaf(xp[i], a, sh), 0.f);
    __shared__ float red[256];
    red[threadIdx.x] = s;
    __syncthreads();
    for (int st = 128; st > 0; st >>= 1) {
        if (threadIdx.x < st) red[threadIdx.x] += red[threadIdx.x + st];
        __syncthreads();
    }
    if (threadIdx.x == 0) g_xavg[bc] = red[0] * (1.f / (float)NPIX);
}

// =====================================================================
// Kernel 2: SE gate + exact top-k threshold + compaction
// =====================================================================
__global__ void se_kernel(const float* __restrict__ fc1,
                          const float* __restrict__ fc2,
                          const float* __restrict__ fcb,
                          const int*   inact_p)
{
    __shared__ float sav[256];
    __shared__ float sy[16];
    __shared__ float ssort[256];
    __shared__ int   wcnt[8];
    __shared__ int   woff[9];

    int hb = blockIdx.x;
    int h  = hb >> 4, b = hb & 15;
    int tid = threadIdx.x;

    sav[tid] = g_xavg[b*CIN + tid];
    __syncthreads();

    if (tid < 16) {
        const float* w = fc1 + (h*16 + tid)*256;
        float s = 0.f;
        #pragma unroll 8
        for (int c = 0; c < 256; ++c) s = fmaf(w[c], sav[c], s);
        sy[tid] = fmaxf(s, 0.f);
    }
    __syncthreads();

    float m;
    {
        const float* w = fc2 + ((size_t)(h*256 + tid)) * 16;
        float s = fcb[h*256 + tid];
        #pragma unroll
        for (int r = 0; r < 16; ++r) s = fmaf(w[r], sy[r], s);
        m = fmaxf(s, 0.f);
    }
    ssort[tid] = m;
    __syncthreads();

    sav[tid] = m;
    __syncthreads();
    for (int st = 128; st > 0; st >>= 1) {
        if (tid < st) sav[tid] += sav[tid + st];
        __syncthreads();
    }
    if (tid == 0) g_lasso_part[hb] = sav[0];
    __syncthreads();

    for (int k = 2; k <= 256; k <<= 1) {
        for (int j = k >> 1; j > 0; j >>= 1) {
            int ixj = tid ^ j;
            if (ixj > tid) {
                float va = ssort[tid], vb = ssort[ixj];
                bool up = ((tid & k) == 0);
                if ((va > vb) == up) { ssort[tid] = vb; ssort[ixj] = va; }
            }
            __syncthreads();
        }
    }

    int inact = 192;
    if (inact_p) {
        int iv = *inact_p;
        if (iv < 0 || iv > 256) {
            float f = __int_as_float(iv);
            iv = (f >= 0.f && f <= 256.f) ? (int)(f + 0.5f) : 192;
        }
        inact = iv;
    }
    float thresh = (inact > 0) ? ssort[min(inact,256) - 1] : -1e30f;

    bool keep = (m > thresh);
    unsigned ball = __ballot_sync(0xffffffffu, keep);
    int wid = tid >> 5, lane = tid & 31;
    if (lane == 0) wcnt[wid] = __popc(ball);
    __syncthreads();
    if (tid == 0) {
        int o = 0;
        #pragma unroll
        for (int w = 0; w < 8; ++w) { woff[w] = o; o += wcnt[w]; }
        woff[8] = o;
        g_act_cnt[hb] = o;
    }
    __syncthreads();
    int total = woff[8];
    int padded = (total + 15) & ~15;
    if (tid >= total && tid < padded) {
        g_act_idx[hb*256 + tid] = 0;
        g_act_val[hb*256 + tid] = 0.f;
    }
    if (keep) {
        int slot = woff[wid] + __popc(ball & ((1u << lane) - 1));
        g_act_idx[hb*256 + slot] = tid;
        g_act_val[hb*256 + slot] = m;
    }
}

__global__ void lasso_kernel(float* __restrict__ out)
{
    __shared__ float red[64];
    int tid = threadIdx.x;
    red[tid] = g_lasso_part[tid];
    __syncthreads();
    for (int st = 32; st > 0; st >>= 1) {
        if (tid < st) red[tid] += red[tid + st];
        __syncthreads();
    }
    if (tid == 0) out[NOUT] = red[0] * (1.f / (float)(BATCH*CIN));
}

// =====================================================================
// Kernel 3: sparse grouped conv, pre-duplicated-x f32x2 version.
//   x staged as (v,v) pairs; layout off(c) = c*2 + (c>>3)*4 floats,
//   row pitch 150 floats, per-ic block 900 floats.
//   weights [ic16][tap9][pitch 66 oc] -> broadcast LDS.64 pairs.
// grid = (14 row-tiles, 64 hb), block = 256 (8 warps; og=warp, pg=lane<28)
// =====================================================================
#define XDROW   150                 // floats per (ic,row)
#define XDIC    (6*XDROW)           // 900 floats per ic
#define XDSZ    (16*XDIC)           // 14400 floats
#define WPITCH  66
#define WSZ     (144*WPITCH)        // 9504 floats
#define SMEMF   (XDSZ + WSZ + 64*4)

typedef unsigned long long ull;

__device__ __forceinline__ ull fma2(ull a, ull b, ull c) {
    ull d;
    asm("fma.rn.f32x2 %0, %1, %2, %3;" : "=l"(d) : "l"(a), "l"(b), "l"(c));
    return d;
}

__global__ __launch_bounds__(256, 2)
void conv_kernel(const float* __restrict__ x,
                 const float* __restrict__ gmm,
                 const float* __restrict__ bet,
                 const float* __restrict__ mea,
                 const float* __restrict__ var,
                 const float* __restrict__ conv_w,   // [4][64][256][3][3]
                 float* __restrict__ out)
{
    extern __shared__ float smem[];
    float* sxd = smem;                  // duplicated x
    float* sw  = smem + XDSZ;           // weights
    float* sca = sw + WSZ;              // [64]
    float* scb = sca + 64;
    float* scm = scb + 64;
    int*   sch = (int*)(scm + 64);

    int hb = blockIdx.y;
    int h  = hb >> 4, b = hb & 15;
    int r0 = blockIdx.x * 4;

    int tid  = threadIdx.x;
    int og   = tid >> 5;               // warp id = oc group
    int pg   = tid & 31;               // lane; <28 active in compute
    int prow = pg / 7;                 // 0..3 (garbage for pg>=28, guarded)
    int pcol = (pg % 7) * 8;           // 0..48

    int cnt = g_act_cnt[hb];
    int nchunks = (cnt + 15) >> 4;

    // hoist all channel constants (up to 64, zero-padded by se_kernel)
    if (tid < 64) {
        int ch = 0; float mv = 0.f;
        if (tid < cnt) { ch = g_act_idx[hb*256 + tid]; mv = g_act_val[hb*256 + tid]; }
        float a  = gmm[ch] * rsqrtf(var[ch] + BN_EPS);
        sca[tid] = a;
        scb[tid] = bet[ch] - mea[ch] * a;
        scm[tid] = mv;
        sch[tid] = ch;
    }

    ull acc2[4][8];
    #pragma unroll
    for (int a = 0; a < 4; ++a)
        #pragma unroll
        for (int i = 0; i < 8; ++i) acc2[a][i] = 0ull;

    // thread's static x-window offsets (floats): XO(pcol) base
    int xo_base = pcol*2 + ((pcol >> 3) << 2);

    // staging assignments
    int xc  = tid & 63;                // column 0..63 (<60 active)
    int xs0 = tid >> 6;                // strip start 0..3
    // weight staging start: idx = tid, oc = tid/144? use rem/oc incremental
    // (recomputed each chunk below)

    __syncthreads();   // consts visible

    for (int ck = 0; ck < nchunks; ++ck) {
        if (ck) __syncthreads();   // protect smem from previous compute

        // ---- stage duplicated x: strips s = icc*6+rr, thread handles col xc
        if (xc < 60) {
            int icc = 0, rr = xs0;
            int gc = xc - 1;
            #pragma unroll 4
            for (int s = xs0; s < 96; s += 4) {
                int chn = ck*16 + icc;
                float mv = scm[chn];
                int gr = r0 - 1 + rr;
                float v = 0.f;
                if ((unsigned)gr < (unsigned)HH && (unsigned)gc < (unsigned)WW && mv != 0.f) {
                    float xv = x[(((size_t)b*CIN + sch[chn])*HH + gr)*WW + gc];
                    v = fmaxf(fmaf(xv, sca[chn], scb[chn]), 0.f) * mv;
                }
                float* dst = sxd + icc*XDIC + rr*XDROW + xc*2 + ((xc >> 3) << 2);
                *reinterpret_cast<float2*>(dst) = make_float2(v, v);
                rr += 4; if (rr >= 6) { rr -= 6; ++icc; }
            }
        }

        // ---- stage weights: [icc][tap][oc] pitch 66
        {
            int oc  = tid / 144;        // 0 or 1 at start
            int rem = tid - oc*144;
            #pragma unroll 4
            for (int k = 0; k < 36; ++k) {
                int icc = rem / 9;      // 0..15
                int tap = rem - icc*9;
                int chn = sch[ck*16 + icc];
                sw[(icc*9 + tap)*WPITCH + oc] =
                    conv_w[(((size_t)(h*CPER + oc))*CIN + chn)*9 + tap];
                rem += 256;
                while (rem >= 144) { rem -= 144; ++oc; }
            }
        }
        __syncthreads();

        // ---- compute
        if (pg < 28) {
            #pragma unroll 1
            for (int icc = 0; icc < 16; ++icc) {
                const float* xb = sxd + icc*XDIC + prow*XDROW + xo_base;
                const float* wb = sw + icc*9*WPITCH + og*8;
                #pragma unroll
                for (int ky = 0; ky < 3; ++ky) {
                    const ull* xr = reinterpret_cast<const ull*>(xb + ky*XDROW);
                    ull xd[10];
                    #pragma unroll
                    for (int i = 0; i < 8; ++i) xd[i] = xr[i];
                    xd[8] = xr[10];
                    xd[9] = xr[11];
                    #pragma unroll
                    for (int kx = 0; kx < 3; ++kx) {
                        const float* wp = wb + (ky*3 + kx)*WPITCH;
                        ull w0 = *reinterpret_cast<const ull*>(wp + 0);
                        ull w1 = *reinterpret_cast<const ull*>(wp + 2);
                        ull w2 = *reinterpret_cast<const ull*>(wp + 4);
                        ull w3 = *reinterpret_cast<const ull*>(wp + 6);
                        #pragma unroll
                        for (int i = 0; i < 8; ++i) {
                            ull xv = xd[kx + i];
                            acc2[0][i] = fma2(w0, xv, acc2[0][i]);
                            acc2[1][i] = fma2(w1, xv, acc2[1][i]);
                            acc2[2][i] = fma2(w2, xv, acc2[2][i]);
                            acc2[3][i] = fma2(w3, xv, acc2[3][i]);
                        }
                    }
                }
            }
        }
    }

    if (pg < 28) {
        #pragma unroll
        for (int a = 0; a < 4; ++a) {
            float lo[8], hi[8];
            #pragma unroll
            for (int i = 0; i < 8; ++i) {
                unsigned l32, h32;
                asm("mov.b64 {%0, %1}, %2;" : "=r"(l32), "=r"(h32) : "l"(acc2[a][i]));
                lo[i] = __uint_as_float(l32);
                hi[i] = __uint_as_float(h32);
            }
            int oc0 = og*8 + 2*a;
            size_t base0 = (((size_t)b*(HEADS*CPER) + (oc0*HEADS + h))*HH + (r0 + prow))*WW + pcol;
            size_t base1 = (((size_t)b*(HEADS*CPER) + ((oc0+1)*HEADS + h))*HH + (r0 + prow))*WW + pcol;
            *reinterpret_cast<float4*>(out + base0)     = make_float4(lo[0], lo[1], lo[2], lo[3]);
            *reinterpret_cast<float4*>(out + base0 + 4) = make_float4(lo[4], lo[5], lo[6], lo[7]);
            *reinterpret_cast<float4*>(out + base1)     = make_float4(hi[0], hi[1], hi[2], hi[3]);
            *reinterpret_cast<float4*>(out + base1 + 4) = make_float4(hi[4], hi[5], hi[6], hi[7]);
        }
    }
}

// =====================================================================
extern "C" void kernel_launch(void* const* d_in, const int* in_sizes, int n_in,
                              void* d_out, int out_size)
{
    const float* x    = (const float*)d_in[0];
    const float* gmm  = (const float*)d_in[1];
    const float* bet  = (const float*)d_in[2];
    const float* mea  = (const float*)d_in[3];
    const float* var  = (const float*)d_in[4];
    const float* fc1  = (const float*)d_in[5];
    const float* fc2  = (const float*)d_in[6];
    const float* fcb  = (const float*)d_in[7];
    const float* cw   = (const float*)d_in[8];
    const int*   inact = (n_in > 9) ? (const int*)d_in[9] : nullptr;
    float* out = (float*)d_out;

    bn_pool_kernel<<<BATCH*CIN, 256>>>(x, gmm, bet, mea, var);
    se_kernel<<<HB_N, 256>>>(fc1, fc2, fcb, inact);
    if (out_size > NOUT) lasso_kernel<<<1, 64>>>(out);

    size_t smem_bytes = SMEMF * sizeof(float);
    cudaFuncSetAttribute(conv_kernel, cudaFuncAttributeMaxDynamicSharedMemorySize,
                         (int)smem_bytes);
    dim3 grid(HH/4, HB_N);
    conv_kernel<<<grid, 256, smem_bytes>>>(x, gmm, bet, mea, var, cw, out);
}

// round 6
// speedup vs baseline: 1.2419x; 1.2414x over previous
#include <cuda_runtime.h>
#include <cuda_bf16.h>
#include <math.h>
#include <stdint.h>

#define BATCH   16
#define CIN     256
#define HH      56
#define WW      56
#define HEADS   4
#define CPER    64
#define HB_N    64
#define NPIX    3136
#define NOUT    (BATCH*HEADS*CPER*NPIX)
#define BN_EPS  1e-5f

#define PGRID   58
#define PTOT    (PGRID*PGRID)    // 3364
#define NTILES  26
#define PLROWS  246              // 128 + 2*59 halo
#define PITCH_P 18               // bf16 per plane row (16 ic + pad)
#define PITCH_W 72               // bf16 per weight row (64 oc + pad)

// dynamic smem byte offsets
#define OFF_WH   0
#define OFF_WL   20736           // 9*16*72*2
#define OFF_PH   41472
#define OFF_PL   50328           // + 246*18*2
#define OFF_CH   59184
#define OFF_CA   59248
#define OFF_CB   59312
#define OFF_CM   59376
#define SMEM_BYTES 59456

__device__ float g_xavg[BATCH*CIN];
__device__ int   g_act_idx[HB_N*256];
__device__ float g_act_val[HB_N*256];
__device__ int   g_act_cnt[HB_N];
__device__ float g_lasso_part[HB_N];
__device__ uint32_t g_whl[HEADS*9*CIN*CPER];   // packed (hi | lo<<16) bf16 weights

// ------------------------- helpers -------------------------
__device__ __forceinline__ uint32_t smem_u32(const void* p) {
    uint32_t a;
    asm("{ .reg .u64 t; cvta.to.shared.u64 t, %1; cvt.u32.u64 %0, t; }" : "=r"(a) : "l"(p));
    return a;
}
__device__ __forceinline__ uint32_t lds32(uint32_t a) {
    uint32_t v;
    asm("ld.shared.b32 %0, [%1];" : "=r"(v) : "r"(a));
    return v;
}
__device__ __forceinline__ void ldsm2t(uint32_t addr, uint32_t &r0, uint32_t &r1) {
    asm("ldmatrix.sync.aligned.m8n8.x2.trans.shared.b16 {%0,%1}, [%2];"
        : "=r"(r0), "=r"(r1) : "r"(addr));
}
__device__ __forceinline__ void mma16816(float* d, const uint32_t* a, const uint32_t* b) {
    asm("mma.sync.aligned.m16n8k16.row.col.f32.bf16.bf16.f32 "
        "{%0,%1,%2,%3}, {%4,%5,%6,%7}, {%8,%9}, {%0,%1,%2,%3};"
        : "+f"(d[0]), "+f"(d[1]), "+f"(d[2]), "+f"(d[3])
        : "r"(a[0]), "r"(a[1]), "r"(a[2]), "r"(a[3]), "r"(b[0]), "r"(b[1]));
}

// =====================================================================
// Kernel 0: weight bf16 hi/lo split, layout [h][t][c][oc]
// =====================================================================
__global__ void wsplit_kernel(const float* __restrict__ cw)
{
    int idx = blockIdx.x*256 + threadIdx.x;
    if (idx >= HEADS*9*CIN*CPER) return;
    int oc  = idx & 63;
    int c   = (idx >> 6) & 255;
    int ht  = idx >> 14;           // h*9 + t
    int t   = ht % 9;
    int h   = ht / 9;
    float w = cw[(((size_t)(h*CPER + oc))*CIN + c)*9 + t];
    __nv_bfloat16 hi = __float2bfloat16(w);
    float hf = __bfloat162float(hi);
    __nv_bfloat16 lo = __float2bfloat16(w - hf);
    g_whl[idx] = (uint32_t)__bfloat16_as_ushort(hi)
               | ((uint32_t)__bfloat16_as_ushort(lo) << 16);
}

// =====================================================================
// Kernel 1: BN+ReLU fused global average pool
// =====================================================================
__global__ void bn_pool_kernel(const float* __restrict__ x,
                               const float* __restrict__ gmm,
                               const float* __restrict__ bet,
                               const float* __restrict__ mea,
                               const float* __restrict__ var)
{
    int bc = blockIdx.x;
    int c  = bc & (CIN-1);
    float a  = gmm[c] * rsqrtf(var[c] + BN_EPS);
    float sh = bet[c] - mea[c] * a;
    const float* xp = x + (size_t)bc * NPIX;
    float s = 0.f;
    for (int i = threadIdx.x; i < NPIX; i += 256)
        s += fmaxf(fmaf(xp[i], a, sh), 0.f);
    __shared__ float red[256];
    red[threadIdx.x] = s;
    __syncthreads();
    for (int st = 128; st > 0; st >>= 1) {
        if (threadIdx.x < st) red[threadIdx.x] += red[threadIdx.x + st];
        __syncthreads();
    }
    if (threadIdx.x == 0) g_xavg[bc] = red[0] * (1.f / (float)NPIX);
}

// =====================================================================
// Kernel 2: SE gate + exact top-k threshold + compaction
// =====================================================================
__global__ void se_kernel(const float* __restrict__ fc1,
                          const float* __restrict__ fc2,
                          const float* __restrict__ fcb,
                          const int*   inact_p)
{
    __shared__ float sav[256];
    __shared__ float sy[16];
    __shared__ float ssort[256];
    __shared__ int   wcnt[8];
    __shared__ int   woff[9];

    int hb = blockIdx.x;
    int h  = hb >> 4, b = hb & 15;
    int tid = threadIdx.x;

    sav[tid] = g_xavg[b*CIN + tid];
    __syncthreads();

    if (tid < 16) {
        const float* w = fc1 + (h*16 + tid)*256;
        float s = 0.f;
        #pragma unroll 8
        for (int c = 0; c < 256; ++c) s = fmaf(w[c], sav[c], s);
        sy[tid] = fmaxf(s, 0.f);
    }
    __syncthreads();

    float m;
    {
        const float* w = fc2 + ((size_t)(h*256 + tid)) * 16;
        float s = fcb[h*256 + tid];
        #pragma unroll
        for (int r = 0; r < 16; ++r) s = fmaf(w[r], sy[r], s);
        m = fmaxf(s, 0.f);
    }
    ssort[tid] = m;
    __syncthreads();

    sav[tid] = m;
    __syncthreads();
    for (int st = 128; st > 0; st >>= 1) {
        if (tid < st) sav[tid] += sav[tid + st];
        __syncthreads();
    }
    if (tid == 0) g_lasso_part[hb] = sav[0];
    __syncthreads();

    for (int k = 2; k <= 256; k <<= 1) {
        for (int j = k >> 1; j > 0; j >>= 1) {
            int ixj = tid ^ j;
            if (ixj > tid) {
                float va = ssort[tid], vb = ssort[ixj];
                bool up = ((tid & k) == 0);
                if ((va > vb) == up) { ssort[tid] = vb; ssort[ixj] = va; }
            }
            __syncthreads();
        }
    }

    int inact = 192;
    if (inact_p) {
        int iv = *inact_p;
        if (iv < 0 || iv > 256) {
            float f = __int_as_float(iv);
            iv = (f >= 0.f && f <= 256.f) ? (int)(f + 0.5f) : 192;
        }
        inact = iv;
    }
    float thresh = (inact > 0) ? ssort[min(inact,256) - 1] : -1e30f;

    bool keep = (m > thresh);
    unsigned ball = __ballot_sync(0xffffffffu, keep);
    int wid = tid >> 5, lane = tid & 31;
    if (lane == 0) wcnt[wid] = __popc(ball);
    __syncthreads();
    if (tid == 0) {
        int o = 0;
        #pragma unroll
        for (int w = 0; w < 8; ++w) { woff[w] = o; o += wcnt[w]; }
        woff[8] = o;
        g_act_cnt[hb] = o;
    }
    __syncthreads();
    int total = woff[8];
    int padded = (total + 15) & ~15;
    if (tid >= total && tid < padded) {
        g_act_idx[hb*256 + tid] = 0;
        g_act_val[hb*256 + tid] = 0.f;
    }
    if (keep) {
        int slot = woff[wid] + __popc(ball & ((1u << lane) - 1));
        g_act_idx[hb*256 + slot] = tid;
        g_act_val[hb*256 + slot] = m;
    }
}

__global__ void lasso_kernel(float* __restrict__ out)
{
    __shared__ float red[64];
    int tid = threadIdx.x;
    red[tid] = g_lasso_part[tid];
    __syncthreads();
    for (int st = 32; st > 0; st >>= 1) {
        if (tid < st) red[tid] += red[tid + st];
        __syncthreads();
    }
    if (tid == 0) out[NOUT] = red[0] * (1.f / (float)(BATCH*CIN));
}

// =====================================================================
// Kernel 3: sparse grouped conv via mma.sync bf16 3-pass.
//  grid = (26 px tiles, 64 hb), block 256 (8 warps = 4M x 2N).
//  M=128 padded px, N=64 oc, K per chunk = 16 ic x 9 taps.
// =====================================================================
__global__ __launch_bounds__(256, 2)
void conv_mma_kernel(const float* __restrict__ x,
                     const float* __restrict__ gmm,
                     const float* __restrict__ bet,
                     const float* __restrict__ mea,
                     const float* __restrict__ var,
                     float* __restrict__ out)
{
    extern __shared__ __align__(16) char dsm[];
    __nv_bfloat16* pH = (__nv_bfloat16*)(dsm + OFF_PH);
    __nv_bfloat16* pL = (__nv_bfloat16*)(dsm + OFF_PL);
    uint16_t* wHs = (uint16_t*)(dsm + OFF_WH);
    uint16_t* wLs = (uint16_t*)(dsm + OFF_WL);
    int*   sch = (int*)(dsm + OFF_CH);
    float* sca = (float*)(dsm + OFF_CA);
    float* scb = (float*)(dsm + OFF_CB);
    float* scm = (float*)(dsm + OFF_CM);

    int tid  = threadIdx.x;
    int wid  = tid >> 5, lane = tid & 31;
    int wm   = wid >> 1, wn = wid & 1;
    int grp  = lane >> 2, qd = lane & 3;

    int hb = blockIdx.y;
    int h  = hb >> 4, b = hb & 15;
    int q0 = blockIdx.x * 128;

    // per-thread staging pixel mapping (row p = tid, valid p<246)
    int pg = q0 - 59 + tid;
    bool pin = (tid < PLROWS) && (pg >= 0) && (pg < PTOT);
    int rp = pg / PGRID, cp = pg - rp*PGRID;
    int rr = rp - 1, cc = cp - 1;
    bool xin = pin && ((unsigned)rr < (unsigned)HH) && ((unsigned)cc < (unsigned)WW);
    size_t xoff = (size_t)rr*WW + cc;

    int cnt = g_act_cnt[hb];
    int nchunks = (cnt + 15) >> 4;

    float d[2][4][4];
    #pragma unroll
    for (int mi = 0; mi < 2; ++mi)
        #pragma unroll
        for (int ni = 0; ni < 4; ++ni)
            #pragma unroll
            for (int k = 0; k < 4; ++k) d[mi][ni][k] = 0.f;

    uint32_t smb = smem_u32(dsm);
    // A fragment base addresses (byte)
    int aHbase = (int)(smb + OFF_PH) + ((59 + wm*32 + grp)*PITCH_P + qd*2)*2;
    int aLbase = (int)(smb + OFF_PL) + ((59 + wm*32 + grp)*PITCH_P + qd*2)*2;
    // B ldmatrix lane base addresses
    uint32_t bHbase = smb + OFF_WH + (uint32_t)(((lane & 15)*PITCH_W + wn*32)*2);
    uint32_t bLbase = smb + OFF_WL + (uint32_t)(((lane & 15)*PITCH_W + wn*32)*2);

    #pragma unroll 1
    for (int ck = 0; ck < nchunks; ++ck) {
        if (ck) __syncthreads();
        // ---- channel constants
        if (tid < 16) {
            int slot = ck*16 + tid;
            int ch = 0; float mv = 0.f;
            if (slot < cnt) { ch = g_act_idx[hb*256 + slot]; mv = g_act_val[hb*256 + slot]; }
            float a  = gmm[ch] * rsqrtf(var[ch] + BN_EPS);
            sch[tid] = ch;
            sca[tid] = a;
            scb[tid] = bet[ch] - mea[ch] * a;
            scm[tid] = mv;
        }
        __syncthreads();

        // ---- stage masked-BN plane: 246 rows x 16 ic, bf16 hi/lo
        if (tid < PLROWS) {
            #pragma unroll 1
            for (int ic = 0; ic < 16; ++ic) {
                float v = 0.f;
                float mv = scm[ic];
                if (xin && mv != 0.f) {
                    float xv = x[((size_t)b*CIN + sch[ic])*NPIX + xoff];
                    v = fmaxf(fmaf(xv, sca[ic], scb[ic]), 0.f) * mv;
                }
                __nv_bfloat16 hi = __float2bfloat16(v);
                float lof = v - __bfloat162float(hi);
                pH[tid*PITCH_P + ic] = hi;
                pL[tid*PITCH_P + ic] = __float2bfloat16(lof);
            }
        }

        // ---- stage weights: smem [t][ic][oc] pitch 72
        #pragma unroll 1
        for (int idx = tid; idx < 9*16*64; idx += 256) {
            int oc = idx & 63;
            int ic = (idx >> 6) & 15;
            int t  = idx >> 10;
            uint32_t wv = g_whl[(((h*9 + t)*CIN + sch[ic]) << 6) + oc];
            int ro = (t*16 + ic)*PITCH_W + oc;
            wHs[ro] = (uint16_t)(wv & 0xffffu);
            wLs[ro] = (uint16_t)(wv >> 16);
        }
        __syncthreads();

        // ---- compute: 9 taps x (2 mi x 4 ni) x 3 passes
        #pragma unroll
        for (int t = 0; t < 9; ++t) {
            int ky = t / 3, kx = t - ky*3;
            int shiftB = ((ky - 1)*PGRID + (kx - 1)) * (PITCH_P*2);

            uint32_t ah[2][4], al[2][4];
            #pragma unroll
            for (int mi = 0; mi < 2; ++mi) {
                uint32_t abH = (uint32_t)(aHbase + shiftB + mi*16*PITCH_P*2);
                uint32_t abL = (uint32_t)(aLbase + shiftB + mi*16*PITCH_P*2);
                ah[mi][0] = lds32(abH);
                ah[mi][1] = lds32(abH + 8*PITCH_P*2);
                ah[mi][2] = lds32(abH + 16);
                ah[mi][3] = lds32(abH + 8*PITCH_P*2 + 16);
                al[mi][0] = lds32(abL);
                al[mi][1] = lds32(abL + 8*PITCH_P*2);
                al[mi][2] = lds32(abL + 16);
                al[mi][3] = lds32(abL + 8*PITCH_P*2 + 16);
            }
            uint32_t bh[4][2], bl[4][2];
            #pragma unroll
            for (int ni = 0; ni < 4; ++ni) {
                uint32_t boff = (uint32_t)(t*16*PITCH_W*2 + ni*16);
                ldsm2t(bHbase + boff, bh[ni][0], bh[ni][1]);
                ldsm2t(bLbase + boff, bl[ni][0], bl[ni][1]);
            }
            #pragma unroll
            for (int mi = 0; mi < 2; ++mi)
                #pragma unroll
                for (int ni = 0; ni < 4; ++ni) {
                    mma16816(d[mi][ni], ah[mi], bh[ni]);
                    mma16816(d[mi][ni], ah[mi], bl[ni]);
                    mma16816(d[mi][ni], al[mi], bh[ni]);
                }
        }
    }

    // ---- epilogue: masked scalar stores (out px contiguous per co)
    #pragma unroll
    for (int mi = 0; mi < 2; ++mi) {
        #pragma unroll
        for (int dr = 0; dr < 2; ++dr) {
            int row = wm*32 + mi*16 + dr*8 + grp;
            int q   = q0 + row;
            int rp2 = q / PGRID, cp2 = q - rp2*PGRID;
            bool v = (rp2 >= 1) && (rp2 <= HH) && (cp2 >= 1) && (cp2 <= WW);
            if (v) {
                size_t ob = ((size_t)b*(HEADS*CPER) + h)*NPIX
                          + (size_t)(rp2-1)*WW + (cp2-1);
                #pragma unroll
                for (int ni = 0; ni < 4; ++ni) {
                    int oc = wn*32 + ni*8 + qd*2;
                    out[ob + (size_t)(oc*HEADS)*NPIX]       = d[mi][ni][dr*2 + 0];
                    out[ob + (size_t)((oc+1)*HEADS)*NPIX]   = d[mi][ni][dr*2 + 1];
                }
            }
        }
    }
}

// =====================================================================
extern "C" void kernel_launch(void* const* d_in, const int* in_sizes, int n_in,
                              void* d_out, int out_size)
{
    const float* x    = (const float*)d_in[0];
    const float* gmm  = (const float*)d_in[1];
    const float* bet  = (const float*)d_in[2];
    const float* mea  = (const float*)d_in[3];
    const float* var  = (const float*)d_in[4];
    const float* fc1  = (const float*)d_in[5];
    const float* fc2  = (const float*)d_in[6];
    const float* fcb  = (const float*)d_in[7];
    const float* cw   = (const float*)d_in[8];
    const int*   inact = (n_in > 9) ? (const int*)d_in[9] : nullptr;
    float* out = (float*)d_out;

    bn_pool_kernel<<<BATCH*CIN, 256>>>(x, gmm, bet, mea, var);
    wsplit_kernel<<<(HEADS*9*CIN*CPER + 255)/256, 256>>>(cw);
    se_kernel<<<HB_N, 256>>>(fc1, fc2, fcb, inact);
    if (out_size > NOUT) lasso_kernel<<<1, 64>>>(out);

    cudaFuncSetAttribute(conv_mma_kernel, cudaFuncAttributeMaxDynamicSharedMemorySize,
                         SMEM_BYTES);
    dim3 grid(NTILES, HB_N);
    conv_mma_kernel<<<grid, 256, SMEM_BYTES>>>(x, gmm, bet, mea, var, out);
}

// round 7
// speedup vs baseline: 1.9817x; 1.5956x over previous
#include <cuda_runtime.h>
#include <cuda_bf16.h>
#include <math.h>
#include <stdint.h>

#define BATCH   16
#define CIN     256
#define HH      56
#define WW      56
#define HEADS   4
#define CPER    64
#define HB_N    64
#define NPIX    3136
#define NOUT    (BATCH*HEADS*CPER*NPIX)
#define BN_EPS  1e-5f

#define PGRID   58
#define PTOT    (PGRID*PGRID)
#define NTILES  26
#define PLROWS  246
#define PITCH_P 18               // bf16 per plane row
#define PITCH_W 72               // bf16 per weight row (64 oc + pad), 144B rows

// dynamic smem byte offsets
#define WBYTES   20736           // 144 rows * 144 B
#define OFF_W0H  0
#define OFF_W0L  20736
#define OFF_W1H  41472
#define OFF_W1L  62208
#define OFF_PH   82944           // 246*18*2 = 8856 -> pad 8864
#define OFF_PL   91808
#define OFF_C    100672          // sch[2][16], sca[2][16], scb[2][16], scm[2][16]
#define SMEM_BYTES 101184

__device__ float g_xavg[BATCH*CIN];
__device__ int   g_act_idx[HB_N*256];
__device__ float g_act_val[HB_N*256];
__device__ int   g_act_cnt[HB_N];
__device__ float g_lasso_part[HB_N];
__device__ __align__(16) uint16_t g_wh[HEADS*9*CIN*CPER];  // bf16 hi, [h][t][c][oc]
__device__ __align__(16) uint16_t g_wl[HEADS*9*CIN*CPER];  // bf16 lo

// ------------------------- helpers -------------------------
__device__ __forceinline__ uint32_t smem_u32(const void* p) {
    uint32_t a;
    asm("{ .reg .u64 t; cvta.to.shared.u64 t, %1; cvt.u32.u64 %0, t; }" : "=r"(a) : "l"(p));
    return a;
}
__device__ __forceinline__ uint32_t lds32(uint32_t a) {
    uint32_t v;
    asm("ld.shared.b32 %0, [%1];" : "=r"(v) : "r"(a));
    return v;
}
__device__ __forceinline__ void ldsm2t(uint32_t addr, uint32_t &r0, uint32_t &r1) {
    asm("ldmatrix.sync.aligned.m8n8.x2.trans.shared.b16 {%0,%1}, [%2];"
        : "=r"(r0), "=r"(r1) : "r"(addr));
}
__device__ __forceinline__ void mma16816(float* d, const uint32_t* a, const uint32_t* b) {
    asm("mma.sync.aligned.m16n8k16.row.col.f32.bf16.bf16.f32 "
        "{%0,%1,%2,%3}, {%4,%5,%6,%7}, {%8,%9}, {%0,%1,%2,%3};"
        : "+f"(d[0]), "+f"(d[1]), "+f"(d[2]), "+f"(d[3])
        : "r"(a[0]), "r"(a[1]), "r"(a[2]), "r"(a[3]), "r"(b[0]), "r"(b[1]));
}
__device__ __forceinline__ void cp16(uint32_t dst, const void* src) {
    asm volatile("cp.async.cg.shared.global [%0], [%1], 16;"
                 :: "r"(dst), "l"(src) : "memory");
}

// =====================================================================
// Kernel 0: weight bf16 hi/lo split -> [h][t][c][oc]
// =====================================================================
__global__ void wsplit_kernel(const float* __restrict__ cw)
{
    int idx = blockIdx.x*256 + threadIdx.x;
    if (idx >= HEADS*9*CIN*CPER) return;
    int oc  = idx & 63;
    int c   = (idx >> 6) & 255;
    int ht  = idx >> 14;
    int t   = ht % 9;
    int h   = ht / 9;
    float w = cw[(((size_t)(h*CPER + oc))*CIN + c)*9 + t];
    __nv_bfloat16 hi = __float2bfloat16(w);
    float hf = __bfloat162float(hi);
    __nv_bfloat16 lo = __float2bfloat16(w - hf);
    g_wh[idx] = __bfloat16_as_ushort(hi);
    g_wl[idx] = __bfloat16_as_ushort(lo);
}

// =====================================================================
// Kernel 1: BN+ReLU fused global average pool
// =====================================================================
__global__ void bn_pool_kernel(const float* __restrict__ x,
                               const float* __restrict__ gmm,
                               const float* __restrict__ bet,
                               const float* __restrict__ mea,
                               const float* __restrict__ var)
{
    int bc = blockIdx.x;
    int c  = bc & (CIN-1);
    float a  = gmm[c] * rsqrtf(var[c] + BN_EPS);
    float sh = bet[c] - mea[c] * a;
    const float* xp = x + (size_t)bc * NPIX;
    float s = 0.f;
    for (int i = threadIdx.x; i < NPIX; i += 256)
        s += fmaxf(fmaf(xp[i], a, sh), 0.f);
    __shared__ float red[256];
    red[threadIdx.x] = s;
    __syncthreads();
    for (int st = 128; st > 0; st >>= 1) {
        if (threadIdx.x < st) red[threadIdx.x] += red[threadIdx.x + st];
        __syncthreads();
    }
    if (threadIdx.x == 0) g_xavg[bc] = red[0] * (1.f / (float)NPIX);
}

// =====================================================================
// Kernel 2: SE gate + exact top-k threshold + compaction
// =====================================================================
__global__ void se_kernel(const float* __restrict__ fc1,
                          const float* __restrict__ fc2,
                          const float* __restrict__ fcb,
                          const int*   inact_p)
{
    __shared__ float sav[256];
    __shared__ float sy[16];
    __shared__ float ssort[256];
    __shared__ int   wcnt[8];
    __shared__ int   woff[9];

    int hb = blockIdx.x;
    int h  = hb >> 4, b = hb & 15;
    int tid = threadIdx.x;

    sav[tid] = g_xavg[b*CIN + tid];
    __syncthreads();

    if (tid < 16) {
        const float* w = fc1 + (h*16 + tid)*256;
        float s = 0.f;
        #pragma unroll 8
        for (int c = 0; c < 256; ++c) s = fmaf(w[c], sav[c], s);
        sy[tid] = fmaxf(s, 0.f);
    }
    __syncthreads();

    float m;
    {
        const float* w = fc2 + ((size_t)(h*256 + tid)) * 16;
        float s = fcb[h*256 + tid];
        #pragma unroll
        for (int r = 0; r < 16; ++r) s = fmaf(w[r], sy[r], s);
        m = fmaxf(s, 0.f);
    }
    ssort[tid] = m;
    __syncthreads();

    sav[tid] = m;
    __syncthreads();
    for (int st = 128; st > 0; st >>= 1) {
        if (tid < st) sav[tid] += sav[tid + st];
        __syncthreads();
    }
    if (tid == 0) g_lasso_part[hb] = sav[0];
    __syncthreads();

    for (int k = 2; k <= 256; k <<= 1) {
        for (int j = k >> 1; j > 0; j >>= 1) {
            int ixj = tid ^ j;
            if (ixj > tid) {
                float va = ssort[tid], vb = ssort[ixj];
                bool up = ((tid & k) == 0);
                if ((va > vb) == up) { ssort[tid] = vb; ssort[ixj] = va; }
            }
            __syncthreads();
        }
    }

    int inact = 192;
    if (inact_p) {
        int iv = *inact_p;
        if (iv < 0 || iv > 256) {
            float f = __int_as_float(iv);
            iv = (f >= 0.f && f <= 256.f) ? (int)(f + 0.5f) : 192;
        }
        inact = iv;
    }
    float thresh = (inact > 0) ? ssort[min(inact,256) - 1] : -1e30f;

    bool keep = (m > thresh);
    unsigned ball = __ballot_sync(0xffffffffu, keep);
    int wid = tid >> 5, lane = tid & 31;
    if (lane == 0) wcnt[wid] = __popc(ball);
    __syncthreads();
    if (tid == 0) {
        int o = 0;
        #pragma unroll
        for (int w = 0; w < 8; ++w) { woff[w] = o; o += wcnt[w]; }
        woff[8] = o;
        g_act_cnt[hb] = o;
    }
    __syncthreads();
    int total = woff[8];
    int padded = (total + 15) & ~15;
    if (tid >= total && tid < padded) {
        g_act_idx[hb*256 + tid] = 0;
        g_act_val[hb*256 + tid] = 0.f;
    }
    if (keep) {
        int slot = woff[wid] + __popc(ball & ((1u << lane) - 1));
        g_act_idx[hb*256 + slot] = tid;
        g_act_val[hb*256 + slot] = m;
    }
}

__global__ void lasso_kernel(float* __restrict__ out)
{
    __shared__ float red[64];
    int tid = threadIdx.x;
    red[tid] = g_lasso_part[tid];
    __syncthreads();
    for (int st = 32; st > 0; st >>= 1) {
        if (tid < st) red[tid] += red[tid + st];
        __syncthreads();
    }
    if (tid == 0) out[NOUT] = red[0] * (1.f / (float)(BATCH*CIN));
}

// =====================================================================
// Kernel 3: sparse grouped conv via mma.sync bf16 3-pass,
//  cp.async double-buffered weight staging.
// =====================================================================
__global__ __launch_bounds__(256, 2)
void conv_mma_kernel(const float* __restrict__ x,
                     const float* __restrict__ gmm,
                     const float* __restrict__ bet,
                     const float* __restrict__ mea,
                     const float* __restrict__ var,
                     float* __restrict__ out)
{
    extern __shared__ __align__(16) char dsm[];
    __nv_bfloat16* pH = (__nv_bfloat16*)(dsm + OFF_PH);
    __nv_bfloat16* pL = (__nv_bfloat16*)(dsm + OFF_PL);
    int*   sch = (int*)(dsm + OFF_C);          // [2][16]
    float* sca = (float*)(dsm + OFF_C + 128);  // [2][16]
    float* scb = (float*)(dsm + OFF_C + 256);
    float* scm = (float*)(dsm + OFF_C + 384);

    int tid  = threadIdx.x;
    int wid  = tid >> 5, lane = tid & 31;
    int wm   = wid >> 1, wn = wid & 1;
    int grp  = lane >> 2, qd = lane & 3;

    int hb = blockIdx.y;
    int h  = hb >> 4, b = hb & 15;
    int q0 = blockIdx.x * 128;

    // staging pixel mapping (row p = tid)
    int pg = q0 - 59 + tid;
    bool pin = (tid < PLROWS) && (pg >= 0) && (pg < PTOT);
    int rp = pg / PGRID, cp = pg - rp*PGRID;
    int rr = rp - 1, cc = cp - 1;
    bool xin = pin && ((unsigned)rr < (unsigned)HH) && ((unsigned)cc < (unsigned)WW);
    size_t xoff = (size_t)rr*WW + cc;

    int cnt = g_act_cnt[hb];
    int nchunks = (cnt + 15) >> 4;

    float d[2][4][4];
    #pragma unroll
    for (int mi = 0; mi < 2; ++mi)
        #pragma unroll
        for (int ni = 0; ni < 4; ++ni)
            #pragma unroll
            for (int k = 0; k < 4; ++k) d[mi][ni][k] = 0.f;

    uint32_t smb = smem_u32(dsm);
    int aHbase = (int)(smb + OFF_PH) + ((59 + wm*32 + grp)*PITCH_P + qd*2)*2;
    int aLbase = (int)(smb + OFF_PL) + ((59 + wm*32 + grp)*PITCH_P + qd*2)*2;
    uint32_t laneW = (uint32_t)(((lane & 15)*PITCH_W + wn*32)*2);

    const uint16_t* whBase = g_wh + ((size_t)h*9*CIN << 6);
    const uint16_t* wlBase = g_wl + ((size_t)h*9*CIN << 6);

    // ---- prologue: consts for chunk 0, then cp.async weights chunk 0
    if (tid < 16) {
        int slot = tid;
        int ch = 0; float mv = 0.f;
        if (slot < cnt) { ch = g_act_idx[hb*256 + slot]; mv = g_act_val[hb*256 + slot]; }
        float a  = gmm[ch] * rsqrtf(var[ch] + BN_EPS);
        sch[tid] = ch; sca[tid] = a;
        scb[tid] = bet[ch] - mea[ch] * a; scm[tid] = mv;
    }
    __syncthreads();
    {
        uint32_t wdst = smb + OFF_W0H;
        #pragma unroll
        for (int i = 0; i < 9; ++i) {
            int idx = tid + i*256;                  // 0..2303
            int arr = idx >= 1152;
            int r   = idx - arr*1152;
            int row = r >> 3;                       // 0..143 = t*16+ic
            int seg = r & 7;
            int ic  = row & 15, t = row >> 4;
            const uint16_t* src = (arr ? wlBase : whBase)
                                + (((t*CIN + sch[ic]) << 6) + seg*8);
            cp16(wdst + (uint32_t)(arr*WBYTES + row*144 + seg*16), src);
        }
        asm volatile("cp.async.commit_group;" ::: "memory");
    }

    #pragma unroll 1
    for (int ck = 0; ck < nchunks; ++ck) {
        int buf = ck & 1;
        int cs  = buf * 16;     // const slot base

        // ---- stage masked-BN plane for chunk ck
        if (tid < PLROWS) {
            #pragma unroll 1
            for (int ic = 0; ic < 16; ++ic) {
                float v = 0.f;
                float mv = scm[cs + ic];
                if (xin && mv != 0.f) {
                    float xv = x[((size_t)b*CIN + sch[cs + ic])*NPIX + xoff];
                    v = fmaxf(fmaf(xv, sca[cs + ic], scb[cs + ic]), 0.f) * mv;
                }
                __nv_bfloat16 hi = __float2bfloat16(v);
                float lof = v - __bfloat162float(hi);
                pH[tid*PITCH_P + ic] = hi;
                pL[tid*PITCH_P + ic] = __float2bfloat16(lof);
            }
        }
        // ---- consts for chunk ck+1
        if (ck + 1 < nchunks && tid < 16) {
            int ns = (ck + 1) & 1;
            int slot = (ck+1)*16 + tid;
            int ch = 0; float mv = 0.f;
            if (slot < cnt) { ch = g_act_idx[hb*256 + slot]; mv = g_act_val[hb*256 + slot]; }
            float a  = gmm[ch] * rsqrtf(var[ch] + BN_EPS);
            sch[ns*16 + tid] = ch; sca[ns*16 + tid] = a;
            scb[ns*16 + tid] = bet[ch] - mea[ch] * a; scm[ns*16 + tid] = mv;
        }
        __syncthreads();

        // ---- issue cp.async weights for chunk ck+1, wait for chunk ck
        if (ck + 1 < nchunks) {
            int ns = (ck + 1) & 1;
            uint32_t wdst = smb + (ns ? OFF_W1H : OFF_W0H);
            #pragma unroll
            for (int i = 0; i < 9; ++i) {
                int idx = tid + i*256;
                int arr = idx >= 1152;
                int r   = idx - arr*1152;
                int row = r >> 3;
                int seg = r & 7;
                int ic  = row & 15, t = row >> 4;
                const uint16_t* src = (arr ? wlBase : whBase)
                                    + (((t*CIN + sch[ns*16 + ic]) << 6) + seg*8);
                cp16(wdst + (uint32_t)(arr*WBYTES + row*144 + seg*16), src);
            }
            asm volatile("cp.async.commit_group;" ::: "memory");
            asm volatile("cp.async.wait_group 1;" ::: "memory");
        } else {
            asm volatile("cp.async.wait_group 0;" ::: "memory");
        }
        __syncthreads();

        // ---- compute chunk ck
        uint32_t bHbase = smb + (buf ? OFF_W1H : OFF_W0H) + laneW;
        uint32_t bLbase = bHbase + WBYTES;
        #pragma unroll
        for (int t = 0; t < 9; ++t) {
            int ky = t / 3, kx = t - ky*3;
            int shiftB = ((ky - 1)*PGRID + (kx - 1)) * (PITCH_P*2);

            uint32_t ah[2][4], al[2][4];
            #pragma unroll
            for (int mi = 0; mi < 2; ++mi) {
                uint32_t abH = (uint32_t)(aHbase + shiftB + mi*16*PITCH_P*2);
                uint32_t abL = (uint32_t)(aLbase + shiftB + mi*16*PITCH_P*2);
                ah[mi][0] = lds32(abH);
                ah[mi][1] = lds32(abH + 8*PITCH_P*2);
                ah[mi][2] = lds32(abH + 16);
                ah[mi][3] = lds32(abH + 8*PITCH_P*2 + 16);
                al[mi][0] = lds32(abL);
                al[mi][1] = lds32(abL + 8*PITCH_P*2);
                al[mi][2] = lds32(abL + 16);
                al[mi][3] = lds32(abL + 8*PITCH_P*2 + 16);
            }
            uint32_t bh[4][2], bl[4][2];
            #pragma unroll
            for (int ni = 0; ni < 4; ++ni) {
                uint32_t boff = (uint32_t)(t*16*PITCH_W*2 + ni*16);
                ldsm2t(bHbase + boff, bh[ni][0], bh[ni][1]);
                ldsm2t(bLbase + boff, bl[ni][0], bl[ni][1]);
            }
            #pragma unroll
            for (int mi = 0; mi < 2; ++mi)
                #pragma unroll
                for (int ni = 0; ni < 4; ++ni) {
                    mma16816(d[mi][ni], ah[mi], bh[ni]);
                    mma16816(d[mi][ni], ah[mi], bl[ni]);
                    mma16816(d[mi][ni], al[mi], bh[ni]);
                }
        }
        __syncthreads();
    }

    // ---- epilogue
    #pragma unroll
    for (int mi = 0; mi < 2; ++mi) {
        #pragma unroll
        for (int dr = 0; dr < 2; ++dr) {
            int row = wm*32 + mi*16 + dr*8 + grp;
            int q   = q0 + row;
            int rp2 = q / PGRID, cp2 = q - rp2*PGRID;
            bool v = (rp2 >= 1) && (rp2 <= HH) && (cp2 >= 1) && (cp2 <= WW);
            if (v) {
                size_t ob = ((size_t)b*(HEADS*CPER) + h)*NPIX
                          + (size_t)(rp2-1)*WW + (cp2-1);
                #pragma unroll
                for (int ni = 0; ni < 4; ++ni) {
                    int oc = wn*32 + ni*8 + qd*2;
                    out[ob + (size_t)(oc*HEADS)*NPIX]     = d[mi][ni][dr*2 + 0];
                    out[ob + (size_t)((oc+1)*HEADS)*NPIX] = d[mi][ni][dr*2 + 1];
                }
            }
        }
    }
}

// =====================================================================
extern "C" void kernel_launch(void* const* d_in, const int* in_sizes, int n_in,
                              void* d_out, int out_size)
{
    const float* x    = (const float*)d_in[0];
    const float* gmm  = (const float*)d_in[1];
    const float* bet  = (const float*)d_in[2];
    const float* mea  = (const float*)d_in[3];
    const float* var  = (const float*)d_in[4];
    const float* fc1  = (const float*)d_in[5];
    const float* fc2  = (const float*)d_in[6];
    const float* fcb  = (const float*)d_in[7];
    const float* cw   = (const float*)d_in[8];
    const int*   inact = (n_in > 9) ? (const int*)d_in[9] : nullptr;
    float* out = (float*)d_out;

    bn_pool_kernel<<<BATCH*CIN, 256>>>(x, gmm, bet, mea, var);
    wsplit_kernel<<<(HEADS*9*CIN*CPER + 255)/256, 256>>>(cw);
    se_kernel<<<HB_N, 256>>>(fc1, fc2, fcb, inact);

    cudaFuncSetAttribute(conv_mma_kernel, cudaFuncAttributeMaxDynamicSharedMemorySize,
                         SMEM_BYTES);
    dim3 grid(NTILES, HB_N);
    conv_mma_kernel<<<grid, 256, SMEM_BYTES>>>(x, gmm, bet, mea, var, out);

    if (out_size > NOUT) lasso_kernel<<<1, 64>>>(out);
}

// round 9
// speedup vs baseline: 2.8381x; 1.4322x over previous
#include <cuda_runtime.h>
#include <cuda_bf16.h>
#include <math.h>
#include <stdint.h>

#define BATCH   16
#define CIN     256
#define HH      56
#define WW      56
#define HEADS   4
#define CPER    64
#define HB_N    64
#define NPIX    3136
#define NOUT    (BATCH*HEADS*CPER*NPIX)
#define BN_EPS  1e-5f

#define PGRID   58
#define PTOT    (PGRID*PGRID)
#define NTILES  26
#define PLROWS  246
#define PITCH_P 18               // bf16 per plane row
#define PITCH_W 72               // bf16 per weight row (144B rows)

// dynamic smem byte offsets
#define WBYTES   20736           // 144 rows * 144 B
#define OFF_W0H  0
#define OFF_W0L  20736
#define OFF_W1H  41472
#define OFF_W1L  62208
#define OFF_PH   82944
#define OFF_PL   91808
#define OFF_C    100672          // sch[2][16], sca[2][16], scb[2][16], scm[2][16]
#define SMEM_BYTES 101184

__device__ float g_xavg[BATCH*CIN];
__device__ int   g_act_idx[HB_N*256];
__device__ float g_act_val[HB_N*256];
__device__ int   g_act_cnt[HB_N];
__device__ float g_lasso_part[HB_N];
__device__ __align__(16) uint16_t g_wh[HEADS*9*CIN*CPER];  // bf16 hi, [h][t][c][oc]
__device__ __align__(16) uint16_t g_wl[HEADS*9*CIN*CPER];  // bf16 lo

// ------------------------- helpers -------------------------
__device__ __forceinline__ uint32_t smem_u32(const void* p) {
    uint32_t a;
    asm("{ .reg .u64 t; cvta.to.shared.u64 t, %1; cvt.u32.u64 %0, t; }" : "=r"(a) : "l"(p));
    return a;
}
__device__ __forceinline__ uint32_t lds32(uint32_t a) {
    uint32_t v;
    asm("ld.shared.b32 %0, [%1];" : "=r"(v) : "r"(a));
    return v;
}
__device__ __forceinline__ void ldsm2t(uint32_t addr, uint32_t &r0, uint32_t &r1) {
    asm("ldmatrix.sync.aligned.m8n8.x2.trans.shared.b16 {%0,%1}, [%2];"
        : "=r"(r0), "=r"(r1) : "r"(addr));
}
__device__ __forceinline__ void mma16816(float* d, const uint32_t* a, const uint32_t* b) {
    asm("mma.sync.aligned.m16n8k16.row.col.f32.bf16.bf16.f32 "
        "{%0,%1,%2,%3}, {%4,%5,%6,%7}, {%8,%9}, {%0,%1,%2,%3};"
        : "+f"(d[0]), "+f"(d[1]), "+f"(d[2]), "+f"(d[3])
        : "r"(a[0]), "r"(a[1]), "r"(a[2]), "r"(a[3]), "r"(b[0]), "r"(b[1]));
}
__device__ __forceinline__ void cp16(uint32_t dst, const void* src) {
    asm volatile("cp.async.cg.shared.global [%0], [%1], 16;"
                 :: "r"(dst), "l"(src) : "memory");
}
__device__ __forceinline__ uint32_t pack_bf(float e, float o) {
    // low half = bf16(e), high half = bf16(o); RN, identical to __float2bfloat16
    uint32_t r;
    asm("cvt.rn.bf16x2.f32 %0, %1, %2;" : "=r"(r) : "f"(o), "f"(e));
    return r;
}

// =====================================================================
// Kernel 0: weight bf16 hi/lo split -> [h][t][c][oc]
// =====================================================================
__global__ void wsplit_kernel(const float* __restrict__ cw)
{
    int idx = blockIdx.x*256 + threadIdx.x;
    if (idx >= HEADS*9*CIN*CPER) return;
    int oc  = idx & 63;
    int c   = (idx >> 6) & 255;
    int ht  = idx >> 14;
    int t   = ht % 9;
    int h   = ht / 9;
    float w = cw[(((size_t)(h*CPER + oc))*CIN + c)*9 + t];
    __nv_bfloat16 hi = __float2bfloat16(w);
    float hf = __bfloat162float(hi);
    __nv_bfloat16 lo = __float2bfloat16(w - hf);
    g_wh[idx] = __bfloat16_as_ushort(hi);
    g_wl[idx] = __bfloat16_as_ushort(lo);
}

// =====================================================================
// Kernel 1: BN+ReLU fused global average pool
// =====================================================================
__global__ void bn_pool_kernel(const float* __restrict__ x,
                               const float* __restrict__ gmm,
                               const float* __restrict__ bet,
                               const float* __restrict__ mea,
                               const float* __restrict__ var)
{
    int bc = blockIdx.x;
    int c  = bc & (CIN-1);
    float a  = gmm[c] * rsqrtf(var[c] + BN_EPS);
    float sh = bet[c] - mea[c] * a;
    const float* xp = x + (size_t)bc * NPIX;
    float s = 0.f;
    for (int i = threadIdx.x; i < NPIX; i += 256)
        s += fmaxf(fmaf(xp[i], a, sh), 0.f);
    __shared__ float red[256];
    red[threadIdx.x] = s;
    __syncthreads();
    for (int st = 128; st > 0; st >>= 1) {
        if (threadIdx.x < st) red[threadIdx.x] += red[threadIdx.x + st];
        __syncthreads();
    }
    if (threadIdx.x == 0) g_xavg[bc] = red[0] * (1.f / (float)NPIX);
}

// =====================================================================
// Kernel 2: SE gate + exact top-k threshold + compaction
// =====================================================================
__global__ void se_kernel(const float* __restrict__ fc1,
                          const float* __restrict__ fc2,
                          const float* __restrict__ fcb,
                          const int*   inact_p)
{
    __shared__ float sav[256];
    __shared__ float sy[16];
    __shared__ float ssort[256];
    __shared__ int   wcnt[8];
    __shared__ int   woff[9];

    int hb = blockIdx.x;
    int h  = hb >> 4, b = hb & 15;
    int tid = threadIdx.x;

    sav[tid] = g_xavg[b*CIN + tid];
    __syncthreads();

    if (tid < 16) {
        const float* w = fc1 + (h*16 + tid)*256;
        float s = 0.f;
        #pragma unroll 8
        for (int c = 0; c < 256; ++c) s = fmaf(w[c], sav[c], s);
        sy[tid] = fmaxf(s, 0.f);
    }
    __syncthreads();

    float m;
    {
        const float* w = fc2 + ((size_t)(h*256 + tid)) * 16;
        float s = fcb[h*256 + tid];
        #pragma unroll
        for (int r = 0; r < 16; ++r) s = fmaf(w[r], sy[r], s);
        m = fmaxf(s, 0.f);
    }
    ssort[tid] = m;
    __syncthreads();

    sav[tid] = m;
    __syncthreads();
    for (int st = 128; st > 0; st >>= 1) {
        if (tid < st) sav[tid] += sav[tid + st];
        __syncthreads();
    }
    if (tid == 0) g_lasso_part[hb] = sav[0];
    __syncthreads();

    for (int k = 2; k <= 256; k <<= 1) {
        for (int j = k >> 1; j > 0; j >>= 1) {
            int ixj = tid ^ j;
            if (ixj > tid) {
                float va = ssort[tid], vb = ssort[ixj];
                bool up = ((tid & k) == 0);
                if ((va > vb) == up) { ssort[tid] = vb; ssort[ixj] = va; }
            }
            __syncthreads();
        }
    }

    int inact = 192;
    if (inact_p) {
        int iv = *inact_p;
        if (iv < 0 || iv > 256) {
            float f = __int_as_float(iv);
            iv = (f >= 0.f && f <= 256.f) ? (int)(f + 0.5f) : 192;
        }
        inact = iv;
    }
    float thresh = (inact > 0) ? ssort[min(inact,256) - 1] : -1e30f;

    bool keep = (m > thresh);
    unsigned ball = __ballot_sync(0xffffffffu, keep);
    int wid = tid >> 5, lane = tid & 31;
    if (lane == 0) wcnt[wid] = __popc(ball);
    __syncthreads();
    if (tid == 0) {
        int o = 0;
        #pragma unroll
        for (int w = 0; w < 8; ++w) { woff[w] = o; o += wcnt[w]; }
        woff[8] = o;
        g_act_cnt[hb] = o;
    }
    __syncthreads();
    int total = woff[8];
    int padded = (total + 15) & ~15;
    if (tid >= total && tid < padded) {
        g_act_idx[hb*256 + tid] = 0;
        g_act_val[hb*256 + tid] = 0.f;
    }
    if (keep) {
        int slot = woff[wid] + __popc(ball & ((1u << lane) - 1));
        g_act_idx[hb*256 + slot] = tid;
        g_act_val[hb*256 + slot] = m;
    }
}

__global__ void lasso_kernel(float* __restrict__ out)
{
    __shared__ float red[64];
    int tid = threadIdx.x;
    red[tid] = g_lasso_part[tid];
    __syncthreads();
    for (int st = 32; st > 0; st >>= 1) {
        if (tid < st) red[tid] += red[tid + st];
        __syncthreads();
    }
    if (tid == 0) out[NOUT] = red[0] * (1.f / (float)(BATCH*CIN));
}

// =====================================================================
// conv staging helpers
// =====================================================================
struct ConstView { int* sch; float* sca; float* scb; float* scm; };

__device__ __forceinline__ void stage_consts(
    ConstView cv, int slot, int ckbase, int cnt, int hb, int tid,
    const float* gmm, const float* bet, const float* mea, const float* var)
{
    if (tid < 16) {
        int pos = ckbase + tid;
        int ch = 0; float mv = 0.f;
        if (pos < cnt) { ch = g_act_idx[hb*256 + pos]; mv = g_act_val[hb*256 + pos]; }
        float a  = gmm[ch] * rsqrtf(var[ch] + BN_EPS);
        cv.sch[slot*16 + tid] = ch;
        cv.sca[slot*16 + tid] = a;
        cv.scb[slot*16 + tid] = bet[ch] - mea[ch] * a;
        cv.scm[slot*16 + tid] = mv;
    }
}

// batched (MLP=8) plane staging with packed STS.32.
// Out-of-image threads (!xin) must write ZEROS (conv zero padding).
__device__ __forceinline__ void stage_plane(
    ConstView cv, int cs, const float* __restrict__ xb, bool xin, size_t xoff,
    __nv_bfloat16* pH, __nv_bfloat16* pL, int tid)
{
    if (tid >= PLROWS) return;
    if (!xin) {
        #pragma unroll
        for (int j = 0; j < 16; j += 2) {
            int eo = tid*PITCH_P + j;
            *(uint32_t*)&pH[eo] = 0u;
            *(uint32_t*)&pL[eo] = 0u;
        }
        return;
    }
    #pragma unroll
    for (int g = 0; g < 2; ++g) {
        float xv[8];
        #pragma unroll
        for (int j = 0; j < 8; ++j) {
            int ic = cs + g*8 + j;
            xv[j] = xb[(size_t)cv.sch[ic]*NPIX + xoff];
        }
        #pragma unroll
        for (int j = 0; j < 8; j += 2) {
            int ic = cs + g*8 + j;
            float v0 = fmaxf(fmaf(xv[j],   cv.sca[ic],   cv.scb[ic]),   0.f) * cv.scm[ic];
            float v1 = fmaxf(fmaf(xv[j+1], cv.sca[ic+1], cv.scb[ic+1]), 0.f) * cv.scm[ic+1];
            uint32_t hp = pack_bf(v0, v1);
            float h0 = __uint_as_float(hp << 16);
            float h1 = __uint_as_float(hp & 0xffff0000u);
            uint32_t lp = pack_bf(v0 - h0, v1 - h1);
            int eo = tid*PITCH_P + g*8 + j;
            *(uint32_t*)&pH[eo] = hp;
            *(uint32_t*)&pL[eo] = lp;
        }
    }
}

__device__ __forceinline__ void issue_weights(
    ConstView cv, int slot, uint32_t wdst,
    const uint16_t* whBase, const uint16_t* wlBase, int tid)
{
    #pragma unroll
    for (int i = 0; i < 9; ++i) {
        int idx = tid + i*256;                  // 0..2303
        int arr = idx >= 1152;
        int r   = idx - arr*1152;
        int row = r >> 3;                       // t*16+ic
        int seg = r & 7;
        int ic  = row & 15, t = row >> 4;
        const uint16_t* src = (arr ? wlBase : whBase)
                            + (((t*CIN + cv.sch[slot*16 + ic]) << 6) + seg*8);
        cp16(wdst + (uint32_t)(arr*WBYTES + row*144 + seg*16), src);
    }
    asm volatile("cp.async.commit_group;" ::: "memory");
}

// =====================================================================
// Kernel 3: sparse grouped conv via mma.sync bf16 3-pass,
//  cp.async double-buffered weights, batched plane staging.
// =====================================================================
__global__ __launch_bounds__(256, 2)
void conv_mma_kernel(const float* __restrict__ x,
                     const float* __restrict__ gmm,
                     const float* __restrict__ bet,
                     const float* __restrict__ mea,
                     const float* __restrict__ var,
                     float* __restrict__ out)
{
    extern __shared__ __align__(16) char dsm[];
    __nv_bfloat16* pH = (__nv_bfloat16*)(dsm + OFF_PH);
    __nv_bfloat16* pL = (__nv_bfloat16*)(dsm + OFF_PL);
    ConstView cv;
    cv.sch = (int*)(dsm + OFF_C);
    cv.sca = (float*)(dsm + OFF_C + 128);
    cv.scb = (float*)(dsm + OFF_C + 256);
    cv.scm = (float*)(dsm + OFF_C + 384);

    int tid  = threadIdx.x;
    int wid  = tid >> 5, lane = tid & 31;
    int wm   = wid >> 1, wn = wid & 1;
    int grp  = lane >> 2, qd = lane & 3;

    int hb = blockIdx.y;
    int h  = hb >> 4, b = hb & 15;
    int q0 = blockIdx.x * 128;

    // staging pixel mapping (row p = tid)
    int pg = q0 - 59 + tid;
    bool pin = (tid < PLROWS) && (pg >= 0) && (pg < PTOT);
    int rp = pg / PGRID, cp = pg - rp*PGRID;
    int rr = rp - 1, cc = cp - 1;
    bool xin = pin && ((unsigned)rr < (unsigned)HH) && ((unsigned)cc < (unsigned)WW);
    size_t xoff = (size_t)rr*WW + cc;
    const float* xb = x + (size_t)b*CIN*NPIX;

    int cnt = g_act_cnt[hb];
    int nchunks = (cnt + 15) >> 4;

    float d[2][4][4];
    #pragma unroll
    for (int mi = 0; mi < 2; ++mi)
        #pragma unroll
        for (int ni = 0; ni < 4; ++ni)
            #pragma unroll
            for (int k = 0; k < 4; ++k) d[mi][ni][k] = 0.f;

    uint32_t smb = smem_u32(dsm);
    int aHbase = (int)(smb + OFF_PH) + ((59 + wm*32 + grp)*PITCH_P + qd*2)*2;
    int aLbase = (int)(smb + OFF_PL) + ((59 + wm*32 + grp)*PITCH_P + qd*2)*2;
    uint32_t laneW = (uint32_t)(((lane & 15)*PITCH_W + wn*32)*2);

    const uint16_t* whBase = g_wh + ((size_t)h*9*CIN << 6);
    const uint16_t* wlBase = g_wl + ((size_t)h*9*CIN << 6);

    // ---- prologue
    stage_consts(cv, 0, 0, cnt, hb, tid, gmm, bet, mea, var);
    __syncthreads();
    issue_weights(cv, 0, smb + OFF_W0H, whBase, wlBase, tid);
    stage_plane(cv, 0, xb, xin, xoff, pH, pL, tid);
    if (nchunks > 1)
        stage_consts(cv, 1, 16, cnt, hb, tid, gmm, bet, mea, var);
    __syncthreads();

    #pragma unroll 1
    for (int ck = 0; ck < nchunks; ++ck) {
        int buf = ck & 1;

        // ---- weights for ck+1 into other buffer; wait for ck
        if (ck + 1 < nchunks) {
            int ns = (ck + 1) & 1;
            issue_weights(cv, ns, smb + (ns ? OFF_W1H : OFF_W0H), whBase, wlBase, tid);
            asm volatile("cp.async.wait_group 1;" ::: "memory");
        } else {
            asm volatile("cp.async.wait_group 0;" ::: "memory");
        }
        __syncthreads();   // B1: weights ck + plane ck (+consts ck+1) visible

        // consts for ck+2 (slot buf is dead: consts ck no longer needed)
        if (ck + 2 < nchunks)
            stage_consts(cv, buf, (ck+2)*16, cnt, hb, tid, gmm, bet, mea, var);

        // ---- compute chunk ck
        uint32_t bHbase = smb + (buf ? OFF_W1H : OFF_W0H) + laneW;
        uint32_t bLbase = bHbase + WBYTES;
        #pragma unroll
        for (int t = 0; t < 9; ++t) {
            int ky = t / 3, kx = t - ky*3;
            int shiftB = ((ky - 1)*PGRID + (kx - 1)) * (PITCH_P*2);

            uint32_t ah[2][4], al[2][4];
            #pragma unroll
            for (int mi = 0; mi < 2; ++mi) {
                uint32_t abH = (uint32_t)(aHbase + shiftB + mi*16*PITCH_P*2);
                uint32_t abL = (uint32_t)(aLbase + shiftB + mi*16*PITCH_P*2);
                ah[mi][0] = lds32(abH);
                ah[mi][1] = lds32(abH + 8*PITCH_P*2);
                ah[mi][2] = lds32(abH + 16);
                ah[mi][3] = lds32(abH + 8*PITCH_P*2 + 16);
                al[mi][0] = lds32(abL);
                al[mi][1] = lds32(abL + 8*PITCH_P*2);
                al[mi][2] = lds32(abL + 16);
                al[mi][3] = lds32(abL + 8*PITCH_P*2 + 16);
            }
            uint32_t bh[4][2], bl[4][2];
            #pragma unroll
            for (int ni = 0; ni < 4; ++ni) {
                uint32_t boff = (uint32_t)(t*16*PITCH_W*2 + ni*16);
                ldsm2t(bHbase + boff, bh[ni][0], bh[ni][1]);
                ldsm2t(bLbase + boff, bl[ni][0], bl[ni][1]);
            }
            #pragma unroll
            for (int mi = 0; mi < 2; ++mi)
                #pragma unroll
                for (int ni = 0; ni < 4; ++ni) {
                    mma16816(d[mi][ni], ah[mi], bh[ni]);
                    mma16816(d[mi][ni], ah[mi], bl[ni]);
                    mma16816(d[mi][ni], al[mi], bh[ni]);
                }
        }

        // ---- stage plane ck+1 (same buffer, after everyone is done reading)
        if (ck + 1 < nchunks) {
            __syncthreads();  // B2: compute done; consts ck+2 visible next iter
            stage_plane(cv, ((ck+1) & 1)*16, xb, xin, xoff, pH, pL, tid);
        }
    }

    // ---- epilogue
    #pragma unroll
    for (int mi = 0; mi < 2; ++mi) {
        #pragma unroll
        for (int dr = 0; dr < 2; ++dr) {
            int row = wm*32 + mi*16 + dr*8 + grp;
            int q   = q0 + row;
            int rp2 = q / PGRID, cp2 = q - rp2*PGRID;
            bool v = (rp2 >= 1) && (rp2 <= HH) && (cp2 >= 1) && (cp2 <= WW);
            if (v) {
                size_t ob = ((size_t)b*(HEADS*CPER) + h)*NPIX
                          + (size_t)(rp2-1)*WW + (cp2-1);
                #pragma unroll
                for (int ni = 0; ni < 4; ++ni) {
                    int oc = wn*32 + ni*8 + qd*2;
                    out[ob + (size_t)(oc*HEADS)*NPIX]     = d[mi][ni][dr*2 + 0];
                    out[ob + (size_t)((oc+1)*HEADS)*NPIX] = d[mi][ni][dr*2 + 1];
                }
            }
        }
    }
}

// =====================================================================
extern "C" void kernel_launch(void* const* d_in, const int* in_sizes, int n_in,
                              void* d_out, int out_size)
{
    const float* x    = (const float*)d_in[0];
    const float* gmm  = (const float*)d_in[1];
    const float* bet  = (const float*)d_in[2];
    const float* mea  = (const float*)d_in[3];
    const float* var  = (const float*)d_in[4];
    const float* fc1  = (const float*)d_in[5];
    const float* fc2  = (const float*)d_in[6];
    const float* fcb  = (const float*)d_in[7];
    const float* cw   = (const float*)d_in[8];
    const int*   inact = (n_in > 9) ? (const int*)d_in[9] : nullptr;
    float* out = (float*)d_out;

    bn_pool_kernel<<<BATCH*CIN, 256>>>(x, gmm, bet, mea, var);
    wsplit_kernel<<<(HEADS*9*CIN*CPER + 255)/256, 256>>>(cw);
    se_kernel<<<HB_N, 256>>>(fc1, fc2, fcb, inact);

    cudaFuncSetAttribute(conv_mma_kernel, cudaFuncAttributeMaxDynamicSharedMemorySize,
                         SMEM_BYTES);
    dim3 grid(NTILES, HB_N);
    conv_mma_kernel<<<grid, 256, SMEM_BYTES>>>(x, gmm, bet, mea, var, out);

    if (out_size > NOUT) lasso_kernel<<<1, 64>>>(out);
}

// round 10
// speedup vs baseline: 3.2626x; 1.1496x over previous
#include <cuda_runtime.h>
#include <cuda_bf16.h>
#include <math.h>
#include <stdint.h>

#define BATCH   16
#define CIN     256
#define HH      56
#define WW      56
#define HEADS   4
#define CPER    64
#define HB_N    64
#define NPIX    3136
#define NOUT    (BATCH*HEADS*CPER*NPIX)
#define BN_EPS  1e-5f

#define PGRID   58
#define PTOT    (PGRID*PGRID)
#define NTILES  26
#define PLROWS  246
#define PITCH_P 24               // bf16 per plane row (16 ic + 8 pad; 48B, 16B-aligned rows)
#define PITCH_W 72               // bf16 per weight row (144B rows)

// dynamic smem byte offsets
#define WBYTES   20736           // 144 rows * 144 B
#define OFF_W0H  0
#define OFF_W0L  20736
#define OFF_W1H  41472
#define OFF_W1L  62208
#define OFF_PH   82944           // 246*48 = 11808
#define OFF_PL   94752
#define OFF_C    106560          // sch[2][16], sca[2][16], scb[2][16], scm[2][16]
#define SMEM_BYTES 107072

__device__ float g_xavg[BATCH*CIN];
__device__ int   g_act_idx[HB_N*256];
__device__ float g_act_val[HB_N*256];
__device__ int   g_act_cnt[HB_N];
__device__ float g_lasso_part[HB_N];
__device__ int   g_lasso_cnt = 0;
__device__ __align__(16) uint16_t g_wh[HEADS*9*CIN*CPER];  // bf16 hi, [h][t][c][oc]
__device__ __align__(16) uint16_t g_wl[HEADS*9*CIN*CPER];  // bf16 lo

// ------------------------- helpers -------------------------
__device__ __forceinline__ uint32_t smem_u32(const void* p) {
    uint32_t a;
    asm("{ .reg .u64 t; cvta.to.shared.u64 t, %1; cvt.u32.u64 %0, t; }" : "=r"(a) : "l"(p));
    return a;
}
__device__ __forceinline__ void ldsm4(uint32_t addr, uint32_t* r) {
    asm("ldmatrix.sync.aligned.m8n8.x4.shared.b16 {%0,%1,%2,%3}, [%4];"
        : "=r"(r[0]), "=r"(r[1]), "=r"(r[2]), "=r"(r[3]) : "r"(addr));
}
__device__ __forceinline__ void ldsm4t(uint32_t addr, uint32_t* r) {
    asm("ldmatrix.sync.aligned.m8n8.x4.trans.shared.b16 {%0,%1,%2,%3}, [%4];"
        : "=r"(r[0]), "=r"(r[1]), "=r"(r[2]), "=r"(r[3]) : "r"(addr));
}
__device__ __forceinline__ void mma16816(float* d, const uint32_t* a, const uint32_t* b) {
    asm("mma.sync.aligned.m16n8k16.row.col.f32.bf16.bf16.f32 "
        "{%0,%1,%2,%3}, {%4,%5,%6,%7}, {%8,%9}, {%0,%1,%2,%3};"
        : "+f"(d[0]), "+f"(d[1]), "+f"(d[2]), "+f"(d[3])
        : "r"(a[0]), "r"(a[1]), "r"(a[2]), "r"(a[3]), "r"(b[0]), "r"(b[1]));
}
__device__ __forceinline__ void cp16(uint32_t dst, const void* src) {
    asm volatile("cp.async.cg.shared.global [%0], [%1], 16;"
                 :: "r"(dst), "l"(src) : "memory");
}
__device__ __forceinline__ uint32_t pack_bf(float e, float o) {
    uint32_t r;
    asm("cvt.rn.bf16x2.f32 %0, %1, %2;" : "=r"(r) : "f"(o), "f"(e));
    return r;
}

// =====================================================================
// Kernel 0: weight bf16 hi/lo split -> [h][t][c][oc]
// =====================================================================
__global__ void wsplit_kernel(const float* __restrict__ cw)
{
    int idx = blockIdx.x*256 + threadIdx.x;
    if (idx >= HEADS*9*CIN*CPER) return;
    int oc  = idx & 63;
    int c   = (idx >> 6) & 255;
    int ht  = idx >> 14;
    int t   = ht % 9;
    int h   = ht / 9;
    float w = cw[(((size_t)(h*CPER + oc))*CIN + c)*9 + t];
    __nv_bfloat16 hi = __float2bfloat16(w);
    float hf = __bfloat162float(hi);
    __nv_bfloat16 lo = __float2bfloat16(w - hf);
    g_wh[idx] = __bfloat16_as_ushort(hi);
    g_wl[idx] = __bfloat16_as_ushort(lo);
}

// =====================================================================
// Kernel 1: BN+ReLU fused global average pool (float4 + shfl reduce)
// =====================================================================
__global__ void bn_pool_kernel(const float* __restrict__ x,
                               const float* __restrict__ gmm,
                               const float* __restrict__ bet,
                               const float* __restrict__ mea,
                               const float* __restrict__ var)
{
    int bc = blockIdx.x;
    int c  = bc & (CIN-1);
    float a  = gmm[c] * rsqrtf(var[c] + BN_EPS);
    float sh = bet[c] - mea[c] * a;
    const float4* xp = (const float4*)(x + (size_t)bc * NPIX);
    float s = 0.f;
    for (int i = threadIdx.x; i < NPIX/4; i += 256) {
        float4 v = xp[i];
        s += fmaxf(fmaf(v.x, a, sh), 0.f) + fmaxf(fmaf(v.y, a, sh), 0.f)
           + fmaxf(fmaf(v.z, a, sh), 0.f) + fmaxf(fmaf(v.w, a, sh), 0.f);
    }
    #pragma unroll
    for (int o = 16; o; o >>= 1) s += __shfl_xor_sync(0xffffffffu, s, o);
    __shared__ float r8[8];
    if ((threadIdx.x & 31) == 0) r8[threadIdx.x >> 5] = s;
    __syncthreads();
    if (threadIdx.x < 8) {
        float v = r8[threadIdx.x];
        #pragma unroll
        for (int o = 4; o; o >>= 1) v += __shfl_xor_sync(0xffu, v, o);
        if (threadIdx.x == 0) g_xavg[bc] = v * (1.f / (float)NPIX);
    }
}

// =====================================================================
// Kernel 2: SE gate + exact top-k threshold + compaction + lasso
// =====================================================================
__global__ void se_kernel(const float* __restrict__ fc1,
                          const float* __restrict__ fc2,
                          const float* __restrict__ fcb,
                          const int*   inact_p,
                          float*       lasso_out)
{
    __shared__ float sav[256];
    __shared__ float sy[16];
    __shared__ float ssort[256];
    __shared__ int   wcnt[8];
    __shared__ int   woff[9];

    int hb = blockIdx.x;
    int h  = hb >> 4, b = hb & 15;
    int tid = threadIdx.x;

    sav[tid] = g_xavg[b*CIN + tid];
    __syncthreads();

    if (tid < 16) {
        const float* w = fc1 + (h*16 + tid)*256;
        float s = 0.f;
        #pragma unroll 8
        for (int c = 0; c < 256; ++c) s = fmaf(w[c], sav[c], s);
        sy[tid] = fmaxf(s, 0.f);
    }
    __syncthreads();

    float m;
    {
        const float* w = fc2 + ((size_t)(h*256 + tid)) * 16;
        float s = fcb[h*256 + tid];
        #pragma unroll
        for (int r = 0; r < 16; ++r) s = fmaf(w[r], sy[r], s);
        m = fmaxf(s, 0.f);
    }
    ssort[tid] = m;
    __syncthreads();

    sav[tid] = m;
    __syncthreads();
    for (int st = 128; st > 0; st >>= 1) {
        if (tid < st) sav[tid] += sav[tid + st];
        __syncthreads();
    }
    if (tid == 0) {
        g_lasso_part[hb] = sav[0];
        __threadfence();
        int ticket = atomicAdd(&g_lasso_cnt, 1);
        if (ticket == HB_N - 1) {
            if (lasso_out) {
                volatile float* vp = g_lasso_part;
                float s = 0.f;
                for (int i = 0; i < HB_N; ++i) s += vp[i];
                *lasso_out = s * (1.f / (float)(BATCH*CIN));
            }
            g_lasso_cnt = 0;   // self-reset for next replay
        }
    }
    __syncthreads();

    for (int k = 2; k <= 256; k <<= 1) {
        for (int j = k >> 1; j > 0; j >>= 1) {
            int ixj = tid ^ j;
            if (ixj > tid) {
                float va = ssort[tid], vb = ssort[ixj];
                bool up = ((tid & k) == 0);
                if ((va > vb) == up) { ssort[tid] = vb; ssort[ixj] = va; }
            }
            __syncthreads();
        }
    }

    int inact = 192;
    if (inact_p) {
        int iv = *inact_p;
        if (iv < 0 || iv > 256) {
            float f = __int_as_float(iv);
            iv = (f >= 0.f && f <= 256.f) ? (int)(f + 0.5f) : 192;
        }
        inact = iv;
    }
    float thresh = (inact > 0) ? ssort[min(inact,256) - 1] : -1e30f;

    bool keep = (m > thresh);
    unsigned ball = __ballot_sync(0xffffffffu, keep);
    int wid = tid >> 5, lane = tid & 31;
    if (lane == 0) wcnt[wid] = __popc(ball);
    __syncthreads();
    if (tid == 0) {
        int o = 0;
        #pragma unroll
        for (int w = 0; w < 8; ++w) { woff[w] = o; o += wcnt[w]; }
        woff[8] = o;
        g_act_cnt[hb] = o;
    }
    __syncthreads();
    int total = woff[8];
    int padded = (total + 15) & ~15;
    if (tid >= total && tid < padded) {
        g_act_idx[hb*256 + tid] = 0;
        g_act_val[hb*256 + tid] = 0.f;
    }
    if (keep) {
        int slot = woff[wid] + __popc(ball & ((1u << lane) - 1));
        g_act_idx[hb*256 + slot] = tid;
        g_act_val[hb*256 + slot] = m;
    }
}

// =====================================================================
// conv staging helpers
// =====================================================================
struct ConstView { int* sch; float* sca; float* scb; float* scm; };

__device__ __forceinline__ void stage_consts(
    ConstView cv, int slot, int ckbase, int cnt, int hb, int tid,
    const float* gmm, const float* bet, const float* mea, const float* var)
{
    if (tid < 16) {
        int pos = ckbase + tid;
        int ch = 0; float mv = 0.f;
        if (pos < cnt) { ch = g_act_idx[hb*256 + pos]; mv = g_act_val[hb*256 + pos]; }
        float a  = gmm[ch] * rsqrtf(var[ch] + BN_EPS);
        cv.sch[slot*16 + tid] = ch;
        cv.sca[slot*16 + tid] = a;
        cv.scb[slot*16 + tid] = bet[ch] - mea[ch] * a;
        cv.scm[slot*16 + tid] = mv;
    }
}

// batched (MLP=8) plane staging with packed STS.32.
// Out-of-image threads (!xin) write ZEROS (conv zero padding).
__device__ __forceinline__ void stage_plane(
    ConstView cv, int cs, const float* __restrict__ xb, bool xin, size_t xoff,
    __nv_bfloat16* pH, __nv_bfloat16* pL, int tid)
{
    if (tid >= PLROWS) return;
    if (!xin) {
        #pragma unroll
        for (int j = 0; j < 16; j += 2) {
            int eo = tid*PITCH_P + j;
            *(uint32_t*)&pH[eo] = 0u;
            *(uint32_t*)&pL[eo] = 0u;
        }
        return;
    }
    #pragma unroll
    for (int g = 0; g < 2; ++g) {
        float xv[8];
        #pragma unroll
        for (int j = 0; j < 8; ++j) {
            int ic = cs + g*8 + j;
            xv[j] = xb[(size_t)cv.sch[ic]*NPIX + xoff];
        }
        #pragma unroll
        for (int j = 0; j < 8; j += 2) {
            int ic = cs + g*8 + j;
            float v0 = fmaxf(fmaf(xv[j],   cv.sca[ic],   cv.scb[ic]),   0.f) * cv.scm[ic];
            float v1 = fmaxf(fmaf(xv[j+1], cv.sca[ic+1], cv.scb[ic+1]), 0.f) * cv.scm[ic+1];
            uint32_t hp = pack_bf(v0, v1);
            float h0 = __uint_as_float(hp << 16);
            float h1 = __uint_as_float(hp & 0xffff0000u);
            uint32_t lp = pack_bf(v0 - h0, v1 - h1);
            int eo = tid*PITCH_P + g*8 + j;
            *(uint32_t*)&pH[eo] = hp;
            *(uint32_t*)&pL[eo] = lp;
        }
    }
}

__device__ __forceinline__ void issue_weights(
    ConstView cv, int slot, uint32_t wdst,
    const uint16_t* whBase, const uint16_t* wlBase, int tid)
{
    #pragma unroll
    for (int i = 0; i < 9; ++i) {
        int idx = tid + i*256;                  // 0..2303
        int arr = idx >= 1152;
        int r   = idx - arr*1152;
        int row = r >> 3;                       // t*16+ic
        int seg = r & 7;
        int ic  = row & 15, t = row >> 4;
        const uint16_t* src = (arr ? wlBase : whBase)
                            + (((t*CIN + cv.sch[slot*16 + ic]) << 6) + seg*8);
        cp16(wdst + (uint32_t)(arr*WBYTES + row*144 + seg*16), src);
    }
    asm volatile("cp.async.commit_group;" ::: "memory");
}

// =====================================================================
// Kernel 3: sparse grouped conv via mma.sync bf16 3-pass,
//  ldmatrix.x4 fragment loads, cp.async double-buffered weights.
// =====================================================================
__global__ __launch_bounds__(256, 2)
void conv_mma_kernel(const float* __restrict__ x,
                     const float* __restrict__ gmm,
                     const float* __restrict__ bet,
                     const float* __restrict__ mea,
                     const float* __restrict__ var,
                     float* __restrict__ out)
{
    extern __shared__ __align__(16) char dsm[];
    __nv_bfloat16* pH = (__nv_bfloat16*)(dsm + OFF_PH);
    __nv_bfloat16* pL = (__nv_bfloat16*)(dsm + OFF_PL);
    ConstView cv;
    cv.sch = (int*)(dsm + OFF_C);
    cv.sca = (float*)(dsm + OFF_C + 128);
    cv.scb = (float*)(dsm + OFF_C + 256);
    cv.scm = (float*)(dsm + OFF_C + 384);

    int tid  = threadIdx.x;
    int wid  = tid >> 5, lane = tid & 31;
    int wm   = wid >> 1, wn = wid & 1;
    int grp  = lane >> 2, qd = lane & 3;

    int hb = blockIdx.y;
    int h  = hb >> 4, b = hb & 15;
    int q0 = blockIdx.x * 128;

    // staging pixel mapping (row p = tid)
    int pg = q0 - 59 + tid;
    bool pin = (tid < PLROWS) && (pg >= 0) && (pg < PTOT);
    int rp = pg / PGRID, cp = pg - rp*PGRID;
    int rr = rp - 1, cc = cp - 1;
    bool xin = pin && ((unsigned)rr < (unsigned)HH) && ((unsigned)cc < (unsigned)WW);
    size_t xoff = (size_t)rr*WW + cc;
    const float* xb = x + (size_t)b*CIN*NPIX;

    int cnt = g_act_cnt[hb];
    int nchunks = (cnt + 15) >> 4;

    float d[2][4][4];
    #pragma unroll
    for (int mi = 0; mi < 2; ++mi)
        #pragma unroll
        for (int ni = 0; ni < 4; ++ni)
            #pragma unroll
            for (int k = 0; k < 4; ++k) d[mi][ni][k] = 0.f;

    uint32_t smb = smem_u32(dsm);
    // ldmatrix lane addresses
    int aRowB = (59 + wm*32 + (lane & 15))*48 + ((lane >> 4) << 4);
    int aH0 = (int)(smb + OFF_PH) + aRowB;
    int aL0 = (int)(smb + OFF_PL) + aRowB;
    uint32_t bLane = (uint32_t)((lane & 15)*144 + wn*64 + ((lane >> 4) << 4));

    const uint16_t* whBase = g_wh + ((size_t)h*9*CIN << 6);
    const uint16_t* wlBase = g_wl + ((size_t)h*9*CIN << 6);

    // ---- prologue
    stage_consts(cv, 0, 0, cnt, hb, tid, gmm, bet, mea, var);
    __syncthreads();
    issue_weights(cv, 0, smb + OFF_W0H, whBase, wlBase, tid);
    stage_plane(cv, 0, xb, xin, xoff, pH, pL, tid);
    if (nchunks > 1)
        stage_consts(cv, 1, 16, cnt, hb, tid, gmm, bet, mea, var);
    __syncthreads();

    #pragma unroll 1
    for (int ck = 0; ck < nchunks; ++ck) {
        int buf = ck & 1;

        // ---- weights for ck+1 into other buffer; wait for ck
        if (ck + 1 < nchunks) {
            int ns = (ck + 1) & 1;
            issue_weights(cv, ns, smb + (ns ? OFF_W1H : OFF_W0H), whBase, wlBase, tid);
            asm volatile("cp.async.wait_group 1;" ::: "memory");
        } else {
            asm volatile("cp.async.wait_group 0;" ::: "memory");
        }
        __syncthreads();   // B1: weights ck + plane ck (+consts ck+1) visible

        // consts for ck+2 (slot buf is dead)
        if (ck + 2 < nchunks)
            stage_consts(cv, buf, (ck+2)*16, cnt, hb, tid, gmm, bet, mea, var);

        // ---- compute chunk ck
        uint32_t bBase = smb + (buf ? OFF_W1H : OFF_W0H) + bLane;
        #pragma unroll
        for (int t = 0; t < 9; ++t) {
            int ky = t / 3, kx = t - ky*3;
            int sb = ((ky - 1)*PGRID + (kx - 1)) * 48;

            uint32_t ah[2][4], al[2][4];
            ldsm4((uint32_t)(aH0 + sb),       ah[0]);
            ldsm4((uint32_t)(aH0 + sb + 768), ah[1]);
            ldsm4((uint32_t)(aL0 + sb),       al[0]);
            ldsm4((uint32_t)(aL0 + sb + 768), al[1]);

            uint32_t bh[4][2], bl[4][2];
            uint32_t bb = bBase + (uint32_t)(t*2304);
            ldsm4t(bb,                 &bh[0][0]);
            ldsm4t(bb + 32,            &bh[2][0]);
            ldsm4t(bb + WBYTES,        &bl[0][0]);
            ldsm4t(bb + WBYTES + 32,   &bl[2][0]);

            #pragma unroll
            for (int mi = 0; mi < 2; ++mi)
                #pragma unroll
                for (int ni = 0; ni < 4; ++ni) {
                    mma16816(d[mi][ni], ah[mi], bh[ni]);
                    mma16816(d[mi][ni], ah[mi], bl[ni]);
                    mma16816(d[mi][ni], al[mi], bh[ni]);
                }
        }

        // ---- stage plane ck+1 (single plane buffer: after compute done)
        if (ck + 1 < nchunks) {
            __syncthreads();  // B2
            stage_plane(cv, ((ck+1) & 1)*16, xb, xin, xoff, pH, pL, tid);
        }
    }

    // ---- epilogue
    #pragma unroll
    for (int mi = 0; mi < 2; ++mi) {
        #pragma unroll
        for (int dr = 0; dr < 2; ++dr) {
            int row = wm*32 + mi*16 + dr*8 + grp;
            int q   = q0 + row;
            int rp2 = q / PGRID, cp2 = q - rp2*PGRID;
            bool v = (rp2 >= 1) && (rp2 <= HH) && (cp2 >= 1) && (cp2 <= WW);
            if (v) {
                size_t ob = ((size_t)b*(HEADS*CPER) + h)*NPIX
                          + (size_t)(rp2-1)*WW + (cp2-1);
                #pragma unroll
                for (int ni = 0; ni < 4; ++ni) {
                    int oc = wn*32 + ni*8 + qd*2;
                    out[ob + (size_t)(oc*HEADS)*NPIX]     = d[mi][ni][dr*2 + 0];
                    out[ob + (size_t)((oc+1)*HEADS)*NPIX] = d[mi][ni][dr*2 + 1];
                }
            }
        }
    }
}

// =====================================================================
extern "C" void kernel_launch(void* const* d_in, const int* in_sizes, int n_in,
                              void* d_out, int out_size)
{
    const float* x    = (const float*)d_in[0];
    const float* gmm  = (const float*)d_in[1];
    const float* bet  = (const float*)d_in[2];
    const float* mea  = (const float*)d_in[3];
    const float* var  = (const float*)d_in[4];
    const float* fc1  = (const float*)d_in[5];
    const float* fc2  = (const float*)d_in[6];
    const float* fcb  = (const float*)d_in[7];
    const float* cw   = (const float*)d_in[8];
    const int*   inact = (n_in > 9) ? (const int*)d_in[9] : nullptr;
    float* out = (float*)d_out;
    float* lasso_out = (out_size > NOUT) ? (out + NOUT) : nullptr;

    bn_pool_kernel<<<BATCH*CIN, 256>>>(x, gmm, bet, mea, var);
    wsplit_kernel<<<(HEADS*9*CIN*CPER + 255)/256, 256>>>(cw);
    se_kernel<<<HB_N, 256>>>(fc1, fc2, fcb, inact, lasso_out);

    cudaFuncSetAttribute(conv_mma_kernel, cudaFuncAttributeMaxDynamicSharedMemorySize,
                         SMEM_BYTES);
    dim3 grid(NTILES, HB_N);
    conv_mma_kernel<<<grid, 256, SMEM_BYTES>>>(x, gmm, bet, mea, var, out);
}